// round 11
// baseline (speedup 1.0000x reference)
#include <cuda_runtime.h>

// ---------------- problem constants ----------------
#define L_   8
#define H_   256
#define W_   448
#define KL_  2
#define KH_  18
#define KW_  32
#define K_   1152              // KL*KH*KW
#define HW_  (H_*W_)           // 114688
#define NPIX (L_*HW_)          // 917504
#define CMAX 840               // max pixels per cell: 4 * 15 * 14

#define T_SCALE   0.625f                       // Kl/(0.4*L)
#define YX_SCALE  ((float)0.17857142857142858) // max(Kh/(0.4*H), Kw/(0.4*W))
#define LAB_SCALE 0.26f

#define EM_THREADS 512
// dynamic smem: sA[27][840] + sR[840] + sF[6][840] = 34*840 floats
#define EM_SMEM    (34 * CMAX * (int)sizeof(float))   // 114240 bytes

// ---------------- device scratch (no allocs allowed) ----------------
__device__ float  g_pF[K_*6*CMAX];     // cell-blocked pixel features [k][c][p] (~23MB)
__device__ float  g_part[K_*189];      // per-block partial sums [k][j*7+c] (c=6 -> weight)
__device__ float4 g_sB4[K_*27*2];      // per-cell neighbor coeffs (invalid j: |sp|^2 += 1e30)

__device__ __forceinline__ float warpSum(float v){
#pragma unroll
    for (int o = 16; o > 0; o >>= 1) v += __shfl_down_sync(0xffffffffu, v, o);
    return v;
}

// fast exp, FMA/ALU pipes only (no MUFU, no F2I). Magic-number round-to-nearest.
__device__ __forceinline__ float fastExp(float u){
    float y = fminf(fmaxf(u * 1.44269504f, -126.0f), 126.0f);
    float z = y + 12582912.0f;              // 2^23 * 1.5 : forces RN to integer
    int   n = __float_as_int(z) - 0x4B400000;
    float f = y - (z - 12582912.0f);        // f in [-0.5, 0.5]
    float p = 1.33336498e-3f;
    p = fmaf(p, f, 9.61817007e-3f);
    p = fmaf(p, f, 5.55041087e-2f);
    p = fmaf(p, f, 2.40226507e-1f);
    p = fmaf(p, f, 6.93147182e-1f);
    p = fmaf(p, f, 1.0f);
    return p * __int_as_float((n + 127) << 23);
}

// cell geometry: t in [4kl,4kl+4), y in [y0,y0+ch), x in [14kw,14kw+14)
__device__ __forceinline__ void cellGeom(int k, int& kl, int& kh, int& kw, int& y0, int& ch){
    kl = k / (KH_*KW_);
    kh = (k / KW_) % KH_;
    kw = k % KW_;
    y0 = (256*kh + 17) / 18;
    int y1 = (256*(kh+1) + 17) / 18;
    ch = y1 - y0;  // 14 or 15
}

// gather spFeat channel c of cell (nl,nh,nw) from g_part (scatter<->gather duality)
__device__ __forceinline__ float gatherPart(int nl, int nh, int nw, int c){
    float v = 0.f;
#pragma unroll
    for (int jj = 0; jj < 27; jj++){
        int bl = nl - (jj/9 - 1), bh = nh - ((jj/3)%3 - 1), bw = nw - (jj%3 - 1);
        if ((unsigned)bl < (unsigned)KL_ &&
            (unsigned)bh < (unsigned)KH_ &&
            (unsigned)bw < (unsigned)KW_){
            int b = (bl*KH_ + bh)*KW_ + bw;
            v += g_part[b*189 + jj*7 + c];
        }
    }
    return v;
}

// ---------------- kernel 1: pFeat + blocked copy + init g_part (center-only) ------
__global__ void __launch_bounds__(256) pa_kernel(const float* __restrict__ lab,
                                                 float* __restrict__ outPF){
    int k = blockIdx.x, tid = threadIdx.x;
    int kl, kh, kw, y0, ch;
    cellGeom(k, kl, kh, kw, y0, ch);
    int P = 56 * ch;  // 4 * ch * 14

    float s0=0.f,s1=0.f,s2=0.f,s3=0.f,s4=0.f,s5=0.f;
    float* gp = &g_pF[(size_t)k*6*CMAX];
#pragma unroll 1
    for (int p = tid; p < P; p += 256){
        int lx = p % 14, q = p / 14, ly = q % ch, lt = q / ch;
        int t = 4*kl + lt, y = y0 + ly, x = 14*kw + lx;
        int pix = t*HW_ + y*W_ + x;
        float f0 = T_SCALE  * (float)t;
        float f1 = YX_SCALE * (float)y;
        float f2 = YX_SCALE * (float)x;
        float f3 = LAB_SCALE * lab[pix];
        float f4 = LAB_SCALE * lab[NPIX + pix];
        float f5 = LAB_SCALE * lab[2*NPIX + pix];
        outPF[pix]          = f0;
        outPF[NPIX+pix]     = f1;
        outPF[2*NPIX+pix]   = f2;
        outPF[3*NPIX+pix]   = f3;
        outPF[4*NPIX+pix]   = f4;
        outPF[5*NPIX+pix]   = f5;
        gp[p]          = f0;
        gp[CMAX+p]     = f1;
        gp[2*CMAX+p]   = f2;
        gp[3*CMAX+p]   = f3;
        gp[4*CMAX+p]   = f4;
        gp[5*CMAX+p]   = f5;
        s0+=f0; s1+=f1; s2+=f2; s3+=f3; s4+=f4; s5+=f5;
    }
    __shared__ float red[6][8];
    __shared__ float sTot[6];
    int wid = tid >> 5, lane = tid & 31;
    float sv[6] = {s0,s1,s2,s3,s4,s5};
#pragma unroll
    for (int c = 0; c < 6; c++){
        float v = warpSum(sv[c]);
        if (lane == 0) red[c][wid] = v;
    }
    __syncthreads();
    if (tid < 6){
        float v = 0.f;
#pragma unroll
        for (int w = 0; w < 8; w++) v += red[tid][w];
        sTot[tid] = v;
    }
    __syncthreads();
    // init g_part: center channel (j=13) holds sums + count; everything else 0
    if (tid < 189){
        float v = 0.f;
        if (tid >= 91 && tid < 98) v = (tid == 97) ? (float)P : sTot[tid - 91];
        g_part[k*189 + tid] = v;
    }
}

// ---------------- kernel 2: fused gather + assoc + accumulate ----------------
// Preamble: gather 27 neighbor spFeats from g_part -> sB (validity baked into |sp|^2)
// Phase A: per-pixel UNNORMALIZED exp -> sA, 1/sum -> sR
// Phase B: warp-per-j-pair dot products with r folded in -> g_part
__global__ void __launch_bounds__(EM_THREADS, 2) em_kernel(){
    extern __shared__ float smem[];     // sA[27*840] | sR[840] | sF[6*840]
    float* sA = smem;
    float* sR = smem + 27*CMAX;
    float* sF = smem + 28*CMAX;
    float* sPart = smem;                // alias: first 27*8 floats of sA (dead until Phase A)
    int k = blockIdx.x, tid = threadIdx.x;
    int kl, kh, kw, y0, ch;
    cellGeom(k, kl, kh, kw, y0, ch);
    int P = 56 * ch;

    __shared__ float sB[27*8];

    // stage 1: 189 threads gather neighbor partial sums (overlapped with feature copy)
    if (tid < 189){
        int j = tid / 7, c = tid - j*7;
        int nl = min(max(kl + (j/9 - 1), 0), KL_-1);
        int nh = min(max(kh + ((j/3)%3 - 1), 0), KH_-1);
        int nw = min(max(kw + (j%3 - 1), 0), KW_-1);
        sPart[j*8 + c] = gatherPart(nl, nh, nw, c);
    }

    // cooperative copy of this block's feature slab (contiguous 6*CMAX floats)
    const float4* gp4 = (const float4*)&g_pF[(size_t)k*6*CMAX];
    float4* sF4 = (float4*)sF;
#pragma unroll 1
    for (int i = tid; i < 6*CMAX/4; i += EM_THREADS) sF4[i] = gp4[i];
    __syncthreads();

    // stage 2: build sB[27][8] = {-2sp[0..5], |sp|^2 (+1e30 if invalid), 0}
    // (sPart is dynamic-smem alias, sB is static smem: no hazard, no intra-warp sync needed)
    if (tid < 27){
        int j = tid;
        bool valid = ((unsigned)(kl + (j/9 - 1)) < (unsigned)KL_) &&
                     ((unsigned)(kh + ((j/3)%3 - 1)) < (unsigned)KH_) &&
                     ((unsigned)(kw + (j%3 - 1)) < (unsigned)KW_);
        float w  = sPart[j*8 + 6];
        float rw = 1.0f / fmaxf(w, 1e-12f);
        float b = 0.f;
#pragma unroll
        for (int c = 0; c < 6; c++){
            float s = sPart[j*8 + c] * rw;
            sB[j*8 + c] = -2.0f * s;
            b = fmaf(s, s, b);
        }
        sB[j*8 + 6] = b + (valid ? 0.f : 1e30f);
        sB[j*8 + 7] = 0.f;
    }
    __syncthreads();

    // ---- Phase A ----
#pragma unroll 1
    for (int p = tid; p < P; p += EM_THREADS){
        float f0 = sF[p],        f1 = sF[CMAX+p],   f2 = sF[2*CMAX+p];
        float f3 = sF[3*CMAX+p], f4 = sF[4*CMAX+p], f5 = sF[5*CMAX+p];
        // shift = distance to own (center, j=13) cell: always valid, small
        float4 c0 = *(const float4*)&sB[13*8];
        float4 c1 = *(const float4*)&sB[13*8 + 4];
        float shift = c1.z;
        shift = fmaf(f0, c0.x, shift);
        shift = fmaf(f1, c0.y, shift);
        shift = fmaf(f2, c0.z, shift);
        shift = fmaf(f3, c0.w, shift);
        shift = fmaf(f4, c1.x, shift);
        shift = fmaf(f5, c1.y, shift);

        float sum = 0.f;
#pragma unroll 3
        for (int j = 0; j < 27; j++){
            float4 b0 = *(const float4*)&sB[j*8];
            float4 b1 = *(const float4*)&sB[j*8 + 4];
            float dd = b1.z;
            dd = fmaf(f0, b0.x, dd);
            dd = fmaf(f1, b0.y, dd);
            dd = fmaf(f2, b0.z, dd);
            dd = fmaf(f3, b0.w, dd);
            dd = fmaf(f4, b1.x, dd);
            dd = fmaf(f5, b1.y, dd);
            float v = fastExp(shift - dd);   // invalid j: dd ~ 1e30 -> v ~ 1e-38 (== 0)
            sA[j*CMAX + p] = v;
            sum += v;
        }
        sR[p] = 1.0f / sum;     // sum >= 1 (center term is exp(0)=1)
    }
    __syncthreads();

    // ---- Phase B: warp handles j and j+16; all operands in SMEM; r folded in ----
    int wid = tid >> 5, lane = tid & 31;
    int j1 = wid, j2 = wid + 16;
    bool has2 = (j2 < 27);
    const float* a1row = &sA[j1*CMAX];
    const float* a2row = &sA[(has2 ? j2 : j1)*CMAX];
    float acc[14];
#pragma unroll
    for (int c = 0; c < 14; c++) acc[c] = 0.f;
#pragma unroll 1
    for (int p = lane; p < P; p += 32){
        float r  = sR[p];
        float a1 = a1row[p] * r;
        float a2 = has2 ? (a2row[p] * r) : 0.0f;
        float f0 = sF[p],        f1 = sF[CMAX+p],   f2 = sF[2*CMAX+p];
        float f3 = sF[3*CMAX+p], f4 = sF[4*CMAX+p], f5 = sF[5*CMAX+p];
        acc[0] = fmaf(a1, f0, acc[0]);
        acc[1] = fmaf(a1, f1, acc[1]);
        acc[2] = fmaf(a1, f2, acc[2]);
        acc[3] = fmaf(a1, f3, acc[3]);
        acc[4] = fmaf(a1, f4, acc[4]);
        acc[5] = fmaf(a1, f5, acc[5]);
        acc[6] += a1;
        acc[7]  = fmaf(a2, f0, acc[7]);
        acc[8]  = fmaf(a2, f1, acc[8]);
        acc[9]  = fmaf(a2, f2, acc[9]);
        acc[10] = fmaf(a2, f3, acc[10]);
        acc[11] = fmaf(a2, f4, acc[11]);
        acc[12] = fmaf(a2, f5, acc[12]);
        acc[13] += a2;
    }
#pragma unroll
    for (int c = 0; c < 7; c++){
        float v = warpSum(acc[c]);
        if (lane == 0) g_part[k*189 + j1*7 + c] = v;
    }
    if (has2){
#pragma unroll
        for (int c = 0; c < 7; c++){
            float v = warpSum(acc[7+c]);
            if (lane == 0) g_part[k*189 + j2*7 + c] = v;
        }
    }
}

// ---------------- kernel 3: build g_sB4 from final g_part + write outSP -----------
__global__ void __launch_bounds__(192) spB2_kernel(float* __restrict__ outSP){
    __shared__ float spF[27][8];
    int k = blockIdx.x, tid = threadIdx.x;
    int kl = k / (KH_*KW_), kh = (k / KW_) % KH_, kw = k % KW_;
    if (tid < 189){
        int j = tid / 7, c = tid - j*7;
        int nl = min(max(kl + (j/9 - 1), 0), KL_-1);
        int nh = min(max(kh + ((j/3)%3 - 1), 0), KH_-1);
        int nw = min(max(kw + (j%3 - 1), 0), KW_-1);
        spF[j][c] = gatherPart(nl, nh, nw, c);
    }
    __syncthreads();
    if (tid < 27){
        int j = tid;
        int dl = j/9 - 1, dh = (j/3)%3 - 1, dw = j%3 - 1;
        bool valid = ((unsigned)(kl+dl) < (unsigned)KL_) &&
                     ((unsigned)(kh+dh) < (unsigned)KH_) &&
                     ((unsigned)(kw+dw) < (unsigned)KW_);
        int nl = min(max(kl+dl, 0), KL_-1);
        int nh = min(max(kh+dh, 0), KH_-1);
        int nw = min(max(kw+dw, 0), KW_-1);
        int nk = (nl*KH_ + nh)*KW_ + nw;
        float rw = 1.0f / fmaxf(spF[j][6], 1e-12f);
        float s[6]; float b = 0.f;
#pragma unroll
        for (int c = 0; c < 6; c++){ s[c] = spF[j][c] * rw; b = fmaf(s[c], s[c], b); }
        g_sB4[(k*27 + j)*2]     = make_float4(-2.f*s[0], -2.f*s[1], -2.f*s[2], -2.f*s[3]);
        g_sB4[(k*27 + j)*2 + 1] = make_float4(-2.f*s[4], -2.f*s[5],
                                              b + (valid ? 0.f : 1e30f), (float)nk);
        if (j == 13){   // own cell: emit spFeat output (transposed [c][k])
#pragma unroll
            for (int c = 0; c < 6; c++) outSP[c*K_ + k] = s[c];
        }
    }
}

// ---------------- kernel 4: final assoc + argmax, global-pixel coalesced ----------------
__global__ void __launch_bounds__(256) final_kernel(const float* __restrict__ outPF,
                                                    float* __restrict__ outA,
                                                    float* __restrict__ outF){
    int pix = blockIdx.x * 256 + threadIdx.x;   // grid = NPIX/256
    int t = pix / HW_; int rr = pix - t*HW_;
    int y = rr / W_;   int x  = rr - y*W_;
    int kl = t >> 2;
    int kh = (y * 18) >> 8;
    int kw = x / 14;
    int k  = (kl*KH_ + kh)*KW_ + kw;

    float f0 = outPF[pix];
    float f1 = outPF[NPIX + pix];
    float f2 = outPF[2*NPIX + pix];
    float f3 = outPF[3*NPIX + pix];
    float f4 = outPF[4*NPIX + pix];
    float f5 = outPF[5*NPIX + pix];

    // shift = center (j=13) distance (always valid)
    float4 c0 = __ldg(&g_sB4[(k*27 + 13)*2]);
    float4 c1 = __ldg(&g_sB4[(k*27 + 13)*2 + 1]);
    float shift = c1.z;
    shift = fmaf(f0, c0.x, shift);
    shift = fmaf(f1, c0.y, shift);
    shift = fmaf(f2, c0.z, shift);
    shift = fmaf(f3, c0.w, shift);
    shift = fmaf(f4, c1.x, shift);
    shift = fmaf(f5, c1.y, shift);

    float e[27]; float nkf[27];
    float sum = 0.f;
#pragma unroll
    for (int j = 0; j < 27; j++){
        float4 b0 = __ldg(&g_sB4[(k*27 + j)*2]);
        float4 b1 = __ldg(&g_sB4[(k*27 + j)*2 + 1]);
        float dd = b1.z;
        dd = fmaf(f0, b0.x, dd);
        dd = fmaf(f1, b0.y, dd);
        dd = fmaf(f2, b0.z, dd);
        dd = fmaf(f3, b0.w, dd);
        dd = fmaf(f4, b1.x, dd);
        dd = fmaf(f5, b1.y, dd);
        float v = fastExp(shift - dd);   // invalid j -> ~1e-38
        e[j] = v; sum += v;
        nkf[j] = b1.w;
    }
    float r = 1.0f / sum;
    float best = -1.f; float bnk = 0.f;
#pragma unroll
    for (int j = 0; j < 27; j++){
        float a = e[j] * r;
        outA[(size_t)j*NPIX + pix] = a;
        if (a > best){ best = a; bnk = nkf[j]; }
    }
    outF[pix] = bnk;
}

// ---------------- launcher ----------------
extern "C" void kernel_launch(void* const* d_in, const int* in_sizes, int n_in,
                              void* d_out, int out_size){
    const float* lab = (const float*)d_in[0];
    if (n_in > 1 && in_sizes[0] != 3*NPIX) lab = (const float*)d_in[1];

    float* out   = (float*)d_out;
    float* outPF = out;                          // 6*N   = 5505024
    float* outSP = out + (size_t)6*NPIX;         // 6*K   = 6912
    float* outA  = outSP + 6*K_;                 // 27*N  = 24772608
    float* outF  = outA + (size_t)27*NPIX;       // N     = 917504

    cudaFuncSetAttribute(em_kernel, cudaFuncAttributeMaxDynamicSharedMemorySize, EM_SMEM);

    pa_kernel<<<K_, 256>>>(lab, outPF);
    for (int it = 0; it < 4; it++)
        em_kernel<<<K_, EM_THREADS, EM_SMEM>>>();
    spB2_kernel<<<K_, 192>>>(outSP);
    final_kernel<<<NPIX/256, 256>>>(outPF, outA, outF);
}

// round 13
// speedup vs baseline: 1.0736x; 1.0736x over previous
#include <cuda_runtime.h>

// ---------------- problem constants ----------------
#define L_   8
#define H_   256
#define W_   448
#define KL_  2
#define KH_  18
#define KW_  32
#define K_   1152              // KL*KH*KW
#define HW_  (H_*W_)           // 114688
#define NPIX (L_*HW_)          // 917504
#define CMAX 840               // max pixels per cell: 4 * 15 * 14

#define T_SCALE   0.625f                       // Kl/(0.4*L)
#define YX_SCALE  ((float)0.17857142857142858) // max(Kh/(0.4*H), Kw/(0.4*W))
#define LAB_SCALE 0.26f

#define EM_THREADS 512
// dynamic smem: sA[27][840] + sR[840] + sF[6][840] = 34*840 floats
#define EM_SMEM    (34 * CMAX * (int)sizeof(float))   // 114240 bytes

// ---------------- device scratch (no allocs allowed) ----------------
__device__ float  g_pF[K_*6*CMAX];     // cell-blocked pixel features [k][c][p] (~23MB)
__device__ float  g_spFeat[K_*6];      // superpixel features [k][c]
__device__ float  g_part[K_*189];      // per-block partial sums [k][j*7+c] (c=6 -> weight)
__device__ float4 g_sB4[K_*27*2];      // per-cell neighbor coeffs: {-2sp[0..3]},{-2sp[4..5],|sp|^2,nk}

__device__ __forceinline__ float warpSum(float v){
#pragma unroll
    for (int o = 16; o > 0; o >>= 1) v += __shfl_down_sync(0xffffffffu, v, o);
    return v;
}

// fast exp, FMA/ALU pipes only. Magic-number rounding; low clamp only
// (argument is bounded above by ~+40 in all call sites).
__device__ __forceinline__ float fastExp(float u){
    float y = fmaxf(u * 1.44269504f, -126.0f);
    float z = y + 12582912.0f;              // 2^23 * 1.5 : forces RN to integer
    int   n = __float_as_int(z) - 0x4B400000;
    float f = y - (z - 12582912.0f);        // f in [-0.5, 0.5]
    float p = 1.33336498e-3f;
    p = fmaf(p, f, 9.61817007e-3f);
    p = fmaf(p, f, 5.55041087e-2f);
    p = fmaf(p, f, 2.40226507e-1f);
    p = fmaf(p, f, 6.93147182e-1f);
    p = fmaf(p, f, 1.0f);
    return p * __int_as_float((n + 127) << 23);
}

// cell geometry: t in [4kl,4kl+4), y in [y0,y0+ch), x in [14kw,14kw+14)
__device__ __forceinline__ void cellGeom(int k, int& kl, int& kh, int& kw, int& y0, int& ch){
    kl = k / (KH_*KW_);
    kh = (k / KW_) % KH_;
    kw = k % KW_;
    y0 = (256*kh + 17) / 18;
    int y1 = (256*(kh+1) + 17) / 18;
    ch = y1 - y0;  // 14 or 15
}

__device__ __forceinline__ unsigned validMask(int kl, int kh, int kw){
    unsigned vmask = 0;
#pragma unroll
    for (int j = 0; j < 27; j++){
        int dl = j/9 - 1, dh = (j/3)%3 - 1, dw = j%3 - 1;
        if ((unsigned)(kl+dl) < (unsigned)KL_ &&
            (unsigned)(kh+dh) < (unsigned)KH_ &&
            (unsigned)(kw+dw) < (unsigned)KW_) vmask |= (1u << j);
    }
    return vmask;
}

// fill sB[27][8]: [0..5] = -2*sp_c, [6] = |sp|^2, [7] pad. tid<27 threads.
__device__ __forceinline__ void fillNbr(int tid, int kl, int kh, int kw, float* sB){
    if (tid < 27){
        int dl = tid/9 - 1, dh = (tid/3)%3 - 1, dw = tid%3 - 1;
        int nl = min(max(kl+dl, 0), KL_-1);
        int nh = min(max(kh+dh, 0), KH_-1);
        int nw = min(max(kw+dw, 0), KW_-1);
        int nk = (nl*KH_ + nh)*KW_ + nw;
        float b = 0.f;
#pragma unroll
        for (int c = 0; c < 6; c++){
            float s = g_spFeat[nk*6 + c];
            sB[tid*8 + c] = -2.0f * s;
            b = fmaf(s, s, b);
        }
        sB[tid*8 + 6] = b;
        sB[tid*8 + 7] = 0.f;
    }
}

// per-pixel softmax numerator pass: dd vs center shift; returns sum; writes sA col
__device__ __forceinline__ float assocCol(const float* __restrict__ sB, unsigned vmask,
                                          float f0, float f1, float f2,
                                          float f3, float f4, float f5,
                                          float shift, float* __restrict__ sA, int p){
    float sum = 0.f;
#pragma unroll 3
    for (int j = 0; j < 27; j++){
        float4 b0 = *(const float4*)&sB[j*8];
        float4 b1 = *(const float4*)&sB[j*8 + 4];
        float dd = b1.z;
        dd = fmaf(f0, b0.x, dd);
        dd = fmaf(f1, b0.y, dd);
        dd = fmaf(f2, b0.z, dd);
        dd = fmaf(f3, b0.w, dd);
        dd = fmaf(f4, b1.x, dd);
        dd = fmaf(f5, b1.y, dd);
        float v = fastExp(shift - dd);
        v = (vmask & (1u << j)) ? v : 0.0f;
        sA[j*CMAX + p] = v;
        sum += v;
    }
    return sum;
}

__device__ __forceinline__ float centerDist(const float* __restrict__ sB,
                                            float f0, float f1, float f2,
                                            float f3, float f4, float f5){
    float4 c0 = *(const float4*)&sB[13*8];
    float4 c1 = *(const float4*)&sB[13*8 + 4];
    float shift = c1.z;
    shift = fmaf(f0, c0.x, shift);
    shift = fmaf(f1, c0.y, shift);
    shift = fmaf(f2, c0.z, shift);
    shift = fmaf(f3, c0.w, shift);
    shift = fmaf(f4, c1.x, shift);
    shift = fmaf(f5, c1.y, shift);
    return shift;
}

// ---------------- kernel 1: pFeat + blocked copy + sp_init mean ----------------
__global__ void __launch_bounds__(256) pa_kernel(const float* __restrict__ lab,
                                                 float* __restrict__ outPF){
    int k = blockIdx.x, tid = threadIdx.x;
    int kl, kh, kw, y0, ch;
    cellGeom(k, kl, kh, kw, y0, ch);
    int P = 56 * ch;  // 4 * ch * 14

    float s0=0.f,s1=0.f,s2=0.f,s3=0.f,s4=0.f,s5=0.f;
    float* gp = &g_pF[(size_t)k*6*CMAX];
#pragma unroll 1
    for (int p = tid; p < P; p += 256){
        int lx = p % 14, q = p / 14, ly = q % ch, lt = q / ch;
        int t = 4*kl + lt, y = y0 + ly, x = 14*kw + lx;
        int pix = t*HW_ + y*W_ + x;
        float f0 = T_SCALE  * (float)t;
        float f1 = YX_SCALE * (float)y;
        float f2 = YX_SCALE * (float)x;
        float f3 = LAB_SCALE * lab[pix];
        float f4 = LAB_SCALE * lab[NPIX + pix];
        float f5 = LAB_SCALE * lab[2*NPIX + pix];
        outPF[pix]          = f0;
        outPF[NPIX+pix]     = f1;
        outPF[2*NPIX+pix]   = f2;
        outPF[3*NPIX+pix]   = f3;
        outPF[4*NPIX+pix]   = f4;
        outPF[5*NPIX+pix]   = f5;
        gp[p]          = f0;
        gp[CMAX+p]     = f1;
        gp[2*CMAX+p]   = f2;
        gp[3*CMAX+p]   = f3;
        gp[4*CMAX+p]   = f4;
        gp[5*CMAX+p]   = f5;
        s0+=f0; s1+=f1; s2+=f2; s3+=f3; s4+=f4; s5+=f5;
    }
    __shared__ float red[6][8];
    int wid = tid >> 5, lane = tid & 31;
    float sv[6] = {s0,s1,s2,s3,s4,s5};
#pragma unroll
    for (int c = 0; c < 6; c++){
        float v = warpSum(sv[c]);
        if (lane == 0) red[c][wid] = v;
    }
    __syncthreads();
    if (tid < 6){
        float v = 0.f;
#pragma unroll
        for (int w = 0; w < 8; w++) v += red[tid][w];
        g_spFeat[k*6 + tid] = v / (float)P;
    }
}

// ---------------- kernel 2: two-phase fused assoc + accumulate ----------------
// Phase A (paired pixels): unnormalized exp -> sA, 1/sum -> sR
// Phase B (9 warps x 3 j-rows): dot products with r folded in -> g_part
__global__ void __launch_bounds__(EM_THREADS, 2) em_kernel(){
    extern __shared__ float smem[];     // sA[27*840] | sR[840] | sF[6*840]
    float* sA = smem;
    float* sR = smem + 27*CMAX;
    float* sF = smem + 28*CMAX;
    int k = blockIdx.x, tid = threadIdx.x;
    int kl, kh, kw, y0, ch;
    cellGeom(k, kl, kh, kw, y0, ch);
    int P = 56 * ch;          // 784 or 840 (always > 512)

    __shared__ float sB[27*8];
    fillNbr(tid, kl, kh, kw, sB);
    unsigned vmask = validMask(kl, kh, kw);

    // cooperative copy of this block's feature slab (contiguous 6*CMAX floats)
    const float4* gp4 = (const float4*)&g_pF[(size_t)k*6*CMAX];
    float4* sF4 = (float4*)sF;
#pragma unroll 1
    for (int i = tid; i < 6*CMAX/4; i += EM_THREADS) sF4[i] = gp4[i];
    __syncthreads();

    // ---- Phase A: thread handles p1 = tid (always valid) and p2 = tid+512 ----
    {
        int p1 = tid, p2 = tid + EM_THREADS;
        float f0 = sF[p1],        f1 = sF[CMAX+p1],   f2 = sF[2*CMAX+p1];
        float f3 = sF[3*CMAX+p1], f4 = sF[4*CMAX+p1], f5 = sF[5*CMAX+p1];
        float sh1 = centerDist(sB, f0, f1, f2, f3, f4, f5);
        if (p2 < P){
            float g0 = sF[p2],        g1 = sF[CMAX+p2],   g2 = sF[2*CMAX+p2];
            float g3 = sF[3*CMAX+p2], g4 = sF[4*CMAX+p2], g5 = sF[5*CMAX+p2];
            float sh2 = centerDist(sB, g0, g1, g2, g3, g4, g5);
            float sum1 = 0.f, sum2 = 0.f;
#pragma unroll 3
            for (int j = 0; j < 27; j++){
                float4 b0 = *(const float4*)&sB[j*8];
                float4 b1 = *(const float4*)&sB[j*8 + 4];
                float d1 = b1.z, d2 = b1.z;
                d1 = fmaf(f0, b0.x, d1);  d2 = fmaf(g0, b0.x, d2);
                d1 = fmaf(f1, b0.y, d1);  d2 = fmaf(g1, b0.y, d2);
                d1 = fmaf(f2, b0.z, d1);  d2 = fmaf(g2, b0.z, d2);
                d1 = fmaf(f3, b0.w, d1);  d2 = fmaf(g3, b0.w, d2);
                d1 = fmaf(f4, b1.x, d1);  d2 = fmaf(g4, b1.x, d2);
                d1 = fmaf(f5, b1.y, d1);  d2 = fmaf(g5, b1.y, d2);
                float v1 = fastExp(sh1 - d1);
                float v2 = fastExp(sh2 - d2);
                v1 = (vmask & (1u << j)) ? v1 : 0.0f;
                v2 = (vmask & (1u << j)) ? v2 : 0.0f;
                sA[j*CMAX + p1] = v1;
                sA[j*CMAX + p2] = v2;
                sum1 += v1; sum2 += v2;
            }
            sR[p1] = 1.0f / sum1;
            sR[p2] = 1.0f / sum2;
        } else {
            float sum1 = assocCol(sB, vmask, f0, f1, f2, f3, f4, f5, sh1, sA, p1);
            sR[p1] = 1.0f / sum1;
        }
    }
    __syncthreads();

    // ---- Phase B: 9 warps, warp w handles j = w, w+9, w+18 ----
    int wid = tid >> 5, lane = tid & 31;
    if (wid < 9){
        int j1 = wid, j2 = wid + 9, j3 = wid + 18;
        const float* a1row = &sA[j1*CMAX];
        const float* a2row = &sA[j2*CMAX];
        const float* a3row = &sA[j3*CMAX];
        float acc[21];
#pragma unroll
        for (int c = 0; c < 21; c++) acc[c] = 0.f;
#pragma unroll 1
        for (int p = lane; p < P; p += 32){
            float r  = sR[p];
            float a1 = a1row[p] * r;
            float a2 = a2row[p] * r;
            float a3 = a3row[p] * r;
            float f0 = sF[p],        f1 = sF[CMAX+p],   f2 = sF[2*CMAX+p];
            float f3 = sF[3*CMAX+p], f4 = sF[4*CMAX+p], f5 = sF[5*CMAX+p];
            acc[0]  = fmaf(a1, f0, acc[0]);
            acc[1]  = fmaf(a1, f1, acc[1]);
            acc[2]  = fmaf(a1, f2, acc[2]);
            acc[3]  = fmaf(a1, f3, acc[3]);
            acc[4]  = fmaf(a1, f4, acc[4]);
            acc[5]  = fmaf(a1, f5, acc[5]);
            acc[6] += a1;
            acc[7]  = fmaf(a2, f0, acc[7]);
            acc[8]  = fmaf(a2, f1, acc[8]);
            acc[9]  = fmaf(a2, f2, acc[9]);
            acc[10] = fmaf(a2, f3, acc[10]);
            acc[11] = fmaf(a2, f4, acc[11]);
            acc[12] = fmaf(a2, f5, acc[12]);
            acc[13] += a2;
            acc[14] = fmaf(a3, f0, acc[14]);
            acc[15] = fmaf(a3, f1, acc[15]);
            acc[16] = fmaf(a3, f2, acc[16]);
            acc[17] = fmaf(a3, f3, acc[17]);
            acc[18] = fmaf(a3, f4, acc[18]);
            acc[19] = fmaf(a3, f5, acc[19]);
            acc[20] += a3;
        }
#pragma unroll
        for (int c = 0; c < 7; c++){
            float v = warpSum(acc[c]);
            if (lane == 0) g_part[k*189 + j1*7 + c] = v;
        }
#pragma unroll
        for (int c = 0; c < 7; c++){
            float v = warpSum(acc[7+c]);
            if (lane == 0) g_part[k*189 + j2*7 + c] = v;
        }
#pragma unroll
        for (int c = 0; c < 7; c++){
            float v = warpSum(acc[14+c]);
            if (lane == 0) g_part[k*189 + j3*7 + c] = v;
        }
    }
}

// ---------------- kernel 3: gather partials -> normalized spFeat ----------------
__global__ void norm_kernel(){
    int k = blockIdx.x, lane = threadIdx.x;  // 32 threads, lanes 0..6 used
    int kl, kh, kw, y0, ch;
    cellGeom(k, kl, kh, kw, y0, ch);
    float v = 0.f;
    if (lane < 7){
#pragma unroll
        for (int j = 0; j < 27; j++){
            int dl = j/9 - 1, dh = (j/3)%3 - 1, dw = j%3 - 1;
            int bl = kl - dl, bh = kh - dh, bw = kw - dw;
            if ((unsigned)bl < (unsigned)KL_ &&
                (unsigned)bh < (unsigned)KH_ &&
                (unsigned)bw < (unsigned)KW_){
                int b = (bl*KH_ + bh)*KW_ + bw;
                v += g_part[b*189 + j*7 + lane];
            }
        }
    }
    float w = __shfl_sync(0xffffffffu, v, 6);
    if (lane < 6) g_spFeat[k*6 + lane] = v / fmaxf(w, 1e-12f);
}

// ---------------- kernel 3b: neighbor coeff table + spFeat output ----------------
__global__ void spB_kernel(float* __restrict__ outSP){
    int k = blockIdx.x, j = threadIdx.x;
    if (j < 6) outSP[j*K_ + k] = g_spFeat[k*6 + j];   // spFeat output (transposed)
    if (j >= 27) return;
    int kl = k / (KH_*KW_), kh = (k / KW_) % KH_, kw = k % KW_;
    int dl = j/9 - 1, dh = (j/3)%3 - 1, dw = j%3 - 1;
    int nl = min(max(kl+dl, 0), KL_-1);
    int nh = min(max(kh+dh, 0), KH_-1);
    int nw = min(max(kw+dw, 0), KW_-1);
    int nk = (nl*KH_ + nh)*KW_ + nw;
    float s[6]; float b = 0.f;
#pragma unroll
    for (int c = 0; c < 6; c++){ s[c] = g_spFeat[nk*6 + c]; b = fmaf(s[c], s[c], b); }
    g_sB4[(k*27 + j)*2]     = make_float4(-2.f*s[0], -2.f*s[1], -2.f*s[2], -2.f*s[3]);
    g_sB4[(k*27 + j)*2 + 1] = make_float4(-2.f*s[4], -2.f*s[5], b, (float)nk);
}

// ---------------- kernel 4: final assoc + argmax, global-pixel coalesced ----------------
__global__ void __launch_bounds__(256) final_kernel(const float* __restrict__ outPF,
                                                    float* __restrict__ outA,
                                                    float* __restrict__ outF){
    int pix = blockIdx.x * 256 + threadIdx.x;   // grid = NPIX/256
    int t = pix / HW_; int rr = pix - t*HW_;
    int y = rr / W_;   int x  = rr - y*W_;
    int kl = t >> 2;
    int kh = (y * 18) >> 8;
    int kw = x / 14;
    int k  = (kl*KH_ + kh)*KW_ + kw;
    unsigned vmask = validMask(kl, kh, kw);

    float f0 = outPF[pix];
    float f1 = outPF[NPIX + pix];
    float f2 = outPF[2*NPIX + pix];
    float f3 = outPF[3*NPIX + pix];
    float f4 = outPF[4*NPIX + pix];
    float f5 = outPF[5*NPIX + pix];

    // shift = center (j=13) distance (always valid)
    float4 c0 = __ldg(&g_sB4[(k*27 + 13)*2]);
    float4 c1 = __ldg(&g_sB4[(k*27 + 13)*2 + 1]);
    float shift = c1.z;
    shift = fmaf(f0, c0.x, shift);
    shift = fmaf(f1, c0.y, shift);
    shift = fmaf(f2, c0.z, shift);
    shift = fmaf(f3, c0.w, shift);
    shift = fmaf(f4, c1.x, shift);
    shift = fmaf(f5, c1.y, shift);

    float e[27]; float nkf[27];
    float sum = 0.f;
#pragma unroll
    for (int j = 0; j < 27; j++){
        float4 b0 = __ldg(&g_sB4[(k*27 + j)*2]);
        float4 b1 = __ldg(&g_sB4[(k*27 + j)*2 + 1]);
        float dd = b1.z;
        dd = fmaf(f0, b0.x, dd);
        dd = fmaf(f1, b0.y, dd);
        dd = fmaf(f2, b0.z, dd);
        dd = fmaf(f3, b0.w, dd);
        dd = fmaf(f4, b1.x, dd);
        dd = fmaf(f5, b1.y, dd);
        float v = fastExp(shift - dd);
        v = (vmask & (1u << j)) ? v : 0.0f;
        e[j] = v; sum += v;
        nkf[j] = b1.w;
    }
    float r = 1.0f / sum;
    float best = -1.f; float bnk = 0.f;
#pragma unroll
    for (int j = 0; j < 27; j++){
        float a = e[j] * r;
        outA[(size_t)j*NPIX + pix] = a;
        if (a > best){ best = a; bnk = nkf[j]; }
    }
    outF[pix] = bnk;
}

// ---------------- launcher ----------------
extern "C" void kernel_launch(void* const* d_in, const int* in_sizes, int n_in,
                              void* d_out, int out_size){
    const float* lab = (const float*)d_in[0];
    if (n_in > 1 && in_sizes[0] != 3*NPIX) lab = (const float*)d_in[1];

    float* out   = (float*)d_out;
    float* outPF = out;                          // 6*N   = 5505024
    float* outSP = out + (size_t)6*NPIX;         // 6*K   = 6912
    float* outA  = outSP + 6*K_;                 // 27*N  = 24772608
    float* outF  = outA + (size_t)27*NPIX;       // N     = 917504

    cudaFuncSetAttribute(em_kernel, cudaFuncAttributeMaxDynamicSharedMemorySize, EM_SMEM);

    pa_kernel<<<K_, 256>>>(lab, outPF);
    for (int it = 0; it < 4; it++){
        em_kernel<<<K_, EM_THREADS, EM_SMEM>>>();
        norm_kernel<<<K_, 32>>>();
    }
    spB_kernel<<<K_, 32>>>(outSP);
    final_kernel<<<NPIX/256, 256>>>(outPF, outA, outF);
}

// round 15
// speedup vs baseline: 1.1675x; 1.0875x over previous
#include <cuda_runtime.h>

// ---------------- problem constants ----------------
#define L_   8
#define H_   256
#define W_   448
#define KL_  2
#define KH_  18
#define KW_  32
#define K_   1152              // KL*KH*KW
#define HW_  (H_*W_)           // 114688
#define NPIX (L_*HW_)          // 917504
#define CMAX 840               // max pixels per cell: 4 * 15 * 14

#define T_SCALE   0.625f                       // Kl/(0.4*L)
#define YX_SCALE  ((float)0.17857142857142858) // max(Kh/(0.4*H), Kw/(0.4*W))
#define LAB_SCALE 0.26f

#define EM_THREADS 512
// dynamic smem: sA[27][840] + sR[840] + sF[6][840] = 34*840 floats
#define EM_SMEM    (34 * CMAX * (int)sizeof(float))   // 114240 bytes

// ---------------- device scratch (no allocs allowed) ----------------
__device__ float  g_pF[K_*6*CMAX];     // cell-blocked pixel features [k][c][p] (~23MB)
__device__ float  g_spFeat[K_*6];      // superpixel features [k][c]
__device__ float  g_part[K_*189];      // per-block partial sums [k][j*7+c] (c=6 -> weight)
__device__ float4 g_sB4[K_*27*2];      // per-cell neighbor coeffs: {-2sp[0..3]},{-2sp[4..5],|sp|^2,nk}

__device__ __forceinline__ float warpSum(float v){
#pragma unroll
    for (int o = 16; o > 0; o >>= 1) v += __shfl_down_sync(0xffffffffu, v, o);
    return v;
}

// fast exp, FMA/ALU pipes only. Magic-number rounding; low clamp only
// (argument is bounded above by ~+40 in all call sites).
__device__ __forceinline__ float fastExp(float u){
    float y = fmaxf(u * 1.44269504f, -126.0f);
    float z = y + 12582912.0f;              // 2^23 * 1.5 : forces RN to integer
    int   n = __float_as_int(z) - 0x4B400000;
    float f = y - (z - 12582912.0f);        // f in [-0.5, 0.5]
    float p = 1.33336498e-3f;
    p = fmaf(p, f, 9.61817007e-3f);
    p = fmaf(p, f, 5.55041087e-2f);
    p = fmaf(p, f, 2.40226507e-1f);
    p = fmaf(p, f, 6.93147182e-1f);
    p = fmaf(p, f, 1.0f);
    return p * __int_as_float((n + 127) << 23);
}

// cell geometry: t in [4kl,4kl+4), y in [y0,y0+ch), x in [14kw,14kw+14)
__device__ __forceinline__ void cellGeom(int k, int& kl, int& kh, int& kw, int& y0, int& ch){
    kl = k / (KH_*KW_);
    kh = (k / KW_) % KH_;
    kw = k % KW_;
    y0 = (256*kh + 17) / 18;
    int y1 = (256*(kh+1) + 17) / 18;
    ch = y1 - y0;  // 14 or 15
}

__device__ __forceinline__ unsigned validMask(int kl, int kh, int kw){
    unsigned vmask = 0;
#pragma unroll
    for (int j = 0; j < 27; j++){
        int dl = j/9 - 1, dh = (j/3)%3 - 1, dw = j%3 - 1;
        if ((unsigned)(kl+dl) < (unsigned)KL_ &&
            (unsigned)(kh+dh) < (unsigned)KH_ &&
            (unsigned)(kw+dw) < (unsigned)KW_) vmask |= (1u << j);
    }
    return vmask;
}

// fill sB[27][8]: [0..5] = -2*sp_c, [6] = |sp|^2, [7] pad. tid<27 threads.
__device__ __forceinline__ void fillNbr(int tid, int kl, int kh, int kw, float* sB){
    if (tid < 27){
        int dl = tid/9 - 1, dh = (tid/3)%3 - 1, dw = tid%3 - 1;
        int nl = min(max(kl+dl, 0), KL_-1);
        int nh = min(max(kh+dh, 0), KH_-1);
        int nw = min(max(kw+dw, 0), KW_-1);
        int nk = (nl*KH_ + nh)*KW_ + nw;
        float b = 0.f;
#pragma unroll
        for (int c = 0; c < 6; c++){
            float s = g_spFeat[nk*6 + c];
            sB[tid*8 + c] = -2.0f * s;
            b = fmaf(s, s, b);
        }
        sB[tid*8 + 6] = b;
        sB[tid*8 + 7] = 0.f;
    }
}

// ---------------- kernel 1: pFeat + blocked copy + sp_init mean ----------------
__global__ void __launch_bounds__(256) pa_kernel(const float* __restrict__ lab,
                                                 float* __restrict__ outPF){
    int k = blockIdx.x, tid = threadIdx.x;
    int kl, kh, kw, y0, ch;
    cellGeom(k, kl, kh, kw, y0, ch);
    int P = 56 * ch;  // 4 * ch * 14

    float s0=0.f,s1=0.f,s2=0.f,s3=0.f,s4=0.f,s5=0.f;
    float* gp = &g_pF[(size_t)k*6*CMAX];
#pragma unroll 1
    for (int p = tid; p < P; p += 256){
        int lx = p % 14, q = p / 14, ly = q % ch, lt = q / ch;
        int t = 4*kl + lt, y = y0 + ly, x = 14*kw + lx;
        int pix = t*HW_ + y*W_ + x;
        float f0 = T_SCALE  * (float)t;
        float f1 = YX_SCALE * (float)y;
        float f2 = YX_SCALE * (float)x;
        float f3 = LAB_SCALE * lab[pix];
        float f4 = LAB_SCALE * lab[NPIX + pix];
        float f5 = LAB_SCALE * lab[2*NPIX + pix];
        outPF[pix]          = f0;
        outPF[NPIX+pix]     = f1;
        outPF[2*NPIX+pix]   = f2;
        outPF[3*NPIX+pix]   = f3;
        outPF[4*NPIX+pix]   = f4;
        outPF[5*NPIX+pix]   = f5;
        gp[p]          = f0;
        gp[CMAX+p]     = f1;
        gp[2*CMAX+p]   = f2;
        gp[3*CMAX+p]   = f3;
        gp[4*CMAX+p]   = f4;
        gp[5*CMAX+p]   = f5;
        s0+=f0; s1+=f1; s2+=f2; s3+=f3; s4+=f4; s5+=f5;
    }
    __shared__ float red[6][8];
    int wid = tid >> 5, lane = tid & 31;
    float sv[6] = {s0,s1,s2,s3,s4,s5};
#pragma unroll
    for (int c = 0; c < 6; c++){
        float v = warpSum(sv[c]);
        if (lane == 0) red[c][wid] = v;
    }
    __syncthreads();
    if (tid < 6){
        float v = 0.f;
#pragma unroll
        for (int w = 0; w < 8; w++) v += red[tid][w];
        g_spFeat[k*6 + tid] = v / (float)P;
    }
}

// ---------------- kernel 2: two-phase fused assoc + accumulate (vectorized) ------
// Phase A (adjacent pixel pairs, float2 ld/st): unnormalized exp -> sA, 1/sum -> sR
// Phase B (9 warps x 3 j-rows, float2 loads): dot products with r folded in -> g_part
__global__ void __launch_bounds__(EM_THREADS, 2) em_kernel(){
    extern __shared__ float smem[];     // sA[27*840] | sR[840] | sF[6*840]
    float* sA = smem;
    float* sR = smem + 27*CMAX;
    float* sF = smem + 28*CMAX;
    int k = blockIdx.x, tid = threadIdx.x;
    int kl, kh, kw, y0, ch;
    cellGeom(k, kl, kh, kw, y0, ch);
    int P = 56 * ch;          // 784 or 840 (always even)

    __shared__ float sB[27*8];
    fillNbr(tid, kl, kh, kw, sB);
    unsigned vmask = validMask(kl, kh, kw);

    // cooperative copy of this block's feature slab (contiguous 6*CMAX floats)
    const float4* gp4 = (const float4*)&g_pF[(size_t)k*6*CMAX];
    float4* sF4 = (float4*)sF;
#pragma unroll 1
    for (int i = tid; i < 6*CMAX/4; i += EM_THREADS) sF4[i] = gp4[i];
    __syncthreads();

    // ---- Phase A: thread handles adjacent pixels p1 = 2*tid, p1+1 ----
    {
        int p1 = 2*tid;
        if (p1 < P){
            float2 F0 = *(const float2*)&sF[p1];
            float2 F1 = *(const float2*)&sF[CMAX+p1];
            float2 F2 = *(const float2*)&sF[2*CMAX+p1];
            float2 F3 = *(const float2*)&sF[3*CMAX+p1];
            float2 F4 = *(const float2*)&sF[4*CMAX+p1];
            float2 F5 = *(const float2*)&sF[5*CMAX+p1];
            // center (j=13) distances
            float4 c0 = *(const float4*)&sB[13*8];
            float4 c1 = *(const float4*)&sB[13*8 + 4];
            float sh1 = c1.z, sh2 = c1.z;
            sh1 = fmaf(F0.x, c0.x, sh1);  sh2 = fmaf(F0.y, c0.x, sh2);
            sh1 = fmaf(F1.x, c0.y, sh1);  sh2 = fmaf(F1.y, c0.y, sh2);
            sh1 = fmaf(F2.x, c0.z, sh1);  sh2 = fmaf(F2.y, c0.z, sh2);
            sh1 = fmaf(F3.x, c0.w, sh1);  sh2 = fmaf(F3.y, c0.w, sh2);
            sh1 = fmaf(F4.x, c1.x, sh1);  sh2 = fmaf(F4.y, c1.x, sh2);
            sh1 = fmaf(F5.x, c1.y, sh1);  sh2 = fmaf(F5.y, c1.y, sh2);

            float sum1 = 0.f, sum2 = 0.f;
#pragma unroll 3
            for (int j = 0; j < 27; j++){
                float4 b0 = *(const float4*)&sB[j*8];
                float4 b1 = *(const float4*)&sB[j*8 + 4];
                float d1 = b1.z, d2 = b1.z;
                d1 = fmaf(F0.x, b0.x, d1);  d2 = fmaf(F0.y, b0.x, d2);
                d1 = fmaf(F1.x, b0.y, d1);  d2 = fmaf(F1.y, b0.y, d2);
                d1 = fmaf(F2.x, b0.z, d1);  d2 = fmaf(F2.y, b0.z, d2);
                d1 = fmaf(F3.x, b0.w, d1);  d2 = fmaf(F3.y, b0.w, d2);
                d1 = fmaf(F4.x, b1.x, d1);  d2 = fmaf(F4.y, b1.x, d2);
                d1 = fmaf(F5.x, b1.y, d1);  d2 = fmaf(F5.y, b1.y, d2);
                float v1 = fastExp(sh1 - d1);
                float v2 = fastExp(sh2 - d2);
                v1 = (vmask & (1u << j)) ? v1 : 0.0f;
                v2 = (vmask & (1u << j)) ? v2 : 0.0f;
                *(float2*)&sA[j*CMAX + p1] = make_float2(v1, v2);
                sum1 += v1; sum2 += v2;
            }
            *(float2*)&sR[p1] = make_float2(1.0f / sum1, 1.0f / sum2);
        }
    }
    __syncthreads();

    // ---- Phase B: 9 warps, warp w handles j = w, w+9, w+18; float2 loads ----
    int wid = tid >> 5, lane = tid & 31;
    if (wid < 9){
        int j1 = wid, j2 = wid + 9, j3 = wid + 18;
        const float* a1row = &sA[j1*CMAX];
        const float* a2row = &sA[j2*CMAX];
        const float* a3row = &sA[j3*CMAX];
        float acc[21];
#pragma unroll
        for (int c = 0; c < 21; c++) acc[c] = 0.f;
#pragma unroll 1
        for (int p = lane*2; p < P; p += 64){
            float2 r  = *(const float2*)&sR[p];
            float2 a1 = *(const float2*)&a1row[p];
            float2 a2 = *(const float2*)&a2row[p];
            float2 a3 = *(const float2*)&a3row[p];
            a1.x *= r.x; a1.y *= r.y;
            a2.x *= r.x; a2.y *= r.y;
            a3.x *= r.x; a3.y *= r.y;
            float2 f0 = *(const float2*)&sF[p];
            float2 f1 = *(const float2*)&sF[CMAX+p];
            float2 f2 = *(const float2*)&sF[2*CMAX+p];
            float2 f3 = *(const float2*)&sF[3*CMAX+p];
            float2 f4 = *(const float2*)&sF[4*CMAX+p];
            float2 f5 = *(const float2*)&sF[5*CMAX+p];
            acc[0]  = fmaf(a1.x, f0.x, acc[0]);   acc[0]  = fmaf(a1.y, f0.y, acc[0]);
            acc[1]  = fmaf(a1.x, f1.x, acc[1]);   acc[1]  = fmaf(a1.y, f1.y, acc[1]);
            acc[2]  = fmaf(a1.x, f2.x, acc[2]);   acc[2]  = fmaf(a1.y, f2.y, acc[2]);
            acc[3]  = fmaf(a1.x, f3.x, acc[3]);   acc[3]  = fmaf(a1.y, f3.y, acc[3]);
            acc[4]  = fmaf(a1.x, f4.x, acc[4]);   acc[4]  = fmaf(a1.y, f4.y, acc[4]);
            acc[5]  = fmaf(a1.x, f5.x, acc[5]);   acc[5]  = fmaf(a1.y, f5.y, acc[5]);
            acc[6] += a1.x + a1.y;
            acc[7]  = fmaf(a2.x, f0.x, acc[7]);   acc[7]  = fmaf(a2.y, f0.y, acc[7]);
            acc[8]  = fmaf(a2.x, f1.x, acc[8]);   acc[8]  = fmaf(a2.y, f1.y, acc[8]);
            acc[9]  = fmaf(a2.x, f2.x, acc[9]);   acc[9]  = fmaf(a2.y, f2.y, acc[9]);
            acc[10] = fmaf(a2.x, f3.x, acc[10]);  acc[10] = fmaf(a2.y, f3.y, acc[10]);
            acc[11] = fmaf(a2.x, f4.x, acc[11]);  acc[11] = fmaf(a2.y, f4.y, acc[11]);
            acc[12] = fmaf(a2.x, f5.x, acc[12]);  acc[12] = fmaf(a2.y, f5.y, acc[12]);
            acc[13] += a2.x + a2.y;
            acc[14] = fmaf(a3.x, f0.x, acc[14]);  acc[14] = fmaf(a3.y, f0.y, acc[14]);
            acc[15] = fmaf(a3.x, f1.x, acc[15]);  acc[15] = fmaf(a3.y, f1.y, acc[15]);
            acc[16] = fmaf(a3.x, f2.x, acc[16]);  acc[16] = fmaf(a3.y, f2.y, acc[16]);
            acc[17] = fmaf(a3.x, f3.x, acc[17]);  acc[17] = fmaf(a3.y, f3.y, acc[17]);
            acc[18] = fmaf(a3.x, f4.x, acc[18]);  acc[18] = fmaf(a3.y, f4.y, acc[18]);
            acc[19] = fmaf(a3.x, f5.x, acc[19]);  acc[19] = fmaf(a3.y, f5.y, acc[19]);
            acc[20] += a3.x + a3.y;
        }
#pragma unroll
        for (int c = 0; c < 7; c++){
            float v = warpSum(acc[c]);
            if (lane == 0) g_part[k*189 + j1*7 + c] = v;
        }
#pragma unroll
        for (int c = 0; c < 7; c++){
            float v = warpSum(acc[7+c]);
            if (lane == 0) g_part[k*189 + j2*7 + c] = v;
        }
#pragma unroll
        for (int c = 0; c < 7; c++){
            float v = warpSum(acc[14+c]);
            if (lane == 0) g_part[k*189 + j3*7 + c] = v;
        }
    }
}

// ---------------- kernel 3: gather partials -> normalized spFeat ----------------
__global__ void norm_kernel(){
    int k = blockIdx.x, lane = threadIdx.x;  // 32 threads, lanes 0..6 used
    int kl, kh, kw, y0, ch;
    cellGeom(k, kl, kh, kw, y0, ch);
    float v = 0.f;
    if (lane < 7){
#pragma unroll
        for (int j = 0; j < 27; j++){
            int dl = j/9 - 1, dh = (j/3)%3 - 1, dw = j%3 - 1;
            int bl = kl - dl, bh = kh - dh, bw = kw - dw;
            if ((unsigned)bl < (unsigned)KL_ &&
                (unsigned)bh < (unsigned)KH_ &&
                (unsigned)bw < (unsigned)KW_){
                int b = (bl*KH_ + bh)*KW_ + bw;
                v += g_part[b*189 + j*7 + lane];
            }
        }
    }
    float w = __shfl_sync(0xffffffffu, v, 6);
    if (lane < 6) g_spFeat[k*6 + lane] = v / fmaxf(w, 1e-12f);
}

// ---------------- kernel 3b: neighbor coeff table + spFeat output ----------------
__global__ void spB_kernel(float* __restrict__ outSP){
    int k = blockIdx.x, j = threadIdx.x;
    if (j < 6) outSP[j*K_ + k] = g_spFeat[k*6 + j];   // spFeat output (transposed)
    if (j >= 27) return;
    int kl = k / (KH_*KW_), kh = (k / KW_) % KH_, kw = k % KW_;
    int dl = j/9 - 1, dh = (j/3)%3 - 1, dw = j%3 - 1;
    int nl = min(max(kl+dl, 0), KL_-1);
    int nh = min(max(kh+dh, 0), KH_-1);
    int nw = min(max(kw+dw, 0), KW_-1);
    int nk = (nl*KH_ + nh)*KW_ + nw;
    float s[6]; float b = 0.f;
#pragma unroll
    for (int c = 0; c < 6; c++){ s[c] = g_spFeat[nk*6 + c]; b = fmaf(s[c], s[c], b); }
    g_sB4[(k*27 + j)*2]     = make_float4(-2.f*s[0], -2.f*s[1], -2.f*s[2], -2.f*s[3]);
    g_sB4[(k*27 + j)*2 + 1] = make_float4(-2.f*s[4], -2.f*s[5], b, (float)nk);
}

// ---------------- kernel 4: final assoc + argmax, global-pixel coalesced ----------------
__global__ void __launch_bounds__(256) final_kernel(const float* __restrict__ outPF,
                                                    float* __restrict__ outA,
                                                    float* __restrict__ outF){
    int pix = blockIdx.x * 256 + threadIdx.x;   // grid = NPIX/256
    int t = pix / HW_; int rr = pix - t*HW_;
    int y = rr / W_;   int x  = rr - y*W_;
    int kl = t >> 2;
    int kh = (y * 18) >> 8;
    int kw = x / 14;
    int k  = (kl*KH_ + kh)*KW_ + kw;
    unsigned vmask = validMask(kl, kh, kw);

    float f0 = outPF[pix];
    float f1 = outPF[NPIX + pix];
    float f2 = outPF[2*NPIX + pix];
    float f3 = outPF[3*NPIX + pix];
    float f4 = outPF[4*NPIX + pix];
    float f5 = outPF[5*NPIX + pix];

    // shift = center (j=13) distance (always valid)
    float4 c0 = __ldg(&g_sB4[(k*27 + 13)*2]);
    float4 c1 = __ldg(&g_sB4[(k*27 + 13)*2 + 1]);
    float shift = c1.z;
    shift = fmaf(f0, c0.x, shift);
    shift = fmaf(f1, c0.y, shift);
    shift = fmaf(f2, c0.z, shift);
    shift = fmaf(f3, c0.w, shift);
    shift = fmaf(f4, c1.x, shift);
    shift = fmaf(f5, c1.y, shift);

    float e[27]; float nkf[27];
    float sum = 0.f;
#pragma unroll
    for (int j = 0; j < 27; j++){
        float4 b0 = __ldg(&g_sB4[(k*27 + j)*2]);
        float4 b1 = __ldg(&g_sB4[(k*27 + j)*2 + 1]);
        float dd = b1.z;
        dd = fmaf(f0, b0.x, dd);
        dd = fmaf(f1, b0.y, dd);
        dd = fmaf(f2, b0.z, dd);
        dd = fmaf(f3, b0.w, dd);
        dd = fmaf(f4, b1.x, dd);
        dd = fmaf(f5, b1.y, dd);
        float v = fastExp(shift - dd);
        v = (vmask & (1u << j)) ? v : 0.0f;
        e[j] = v; sum += v;
        nkf[j] = b1.w;
    }
    float r = 1.0f / sum;
    float best = -1.f; float bnk = 0.f;
#pragma unroll
    for (int j = 0; j < 27; j++){
        float a = e[j] * r;
        outA[(size_t)j*NPIX + pix] = a;
        if (a > best){ best = a; bnk = nkf[j]; }
    }
    outF[pix] = bnk;
}

// ---------------- launcher ----------------
extern "C" void kernel_launch(void* const* d_in, const int* in_sizes, int n_in,
                              void* d_out, int out_size){
    const float* lab = (const float*)d_in[0];
    if (n_in > 1 && in_sizes[0] != 3*NPIX) lab = (const float*)d_in[1];

    float* out   = (float*)d_out;
    float* outPF = out;                          // 6*N   = 5505024
    float* outSP = out + (size_t)6*NPIX;         // 6*K   = 6912
    float* outA  = outSP + 6*K_;                 // 27*N  = 24772608
    float* outF  = outA + (size_t)27*NPIX;       // N     = 917504

    cudaFuncSetAttribute(em_kernel, cudaFuncAttributeMaxDynamicSharedMemorySize, EM_SMEM);

    pa_kernel<<<K_, 256>>>(lab, outPF);
    for (int it = 0; it < 4; it++){
        em_kernel<<<K_, EM_THREADS, EM_SMEM>>>();
        norm_kernel<<<K_, 32>>>();
    }
    spB_kernel<<<K_, 32>>>(outSP);
    final_kernel<<<NPIX/256, 256>>>(outPF, outA, outF);
}

// round 16
// speedup vs baseline: 1.1951x; 1.0236x over previous
#include <cuda_runtime.h>

// ---------------- problem constants ----------------
#define L_   8
#define H_   256
#define W_   448
#define KL_  2
#define KH_  18
#define KW_  32
#define K_   1152              // KL*KH*KW
#define HW_  (H_*W_)           // 114688
#define NPIX (L_*HW_)          // 917504
#define CMAX 840               // max pixels per cell: 4 * 15 * 14

#define T_SCALE   0.625f                       // Kl/(0.4*L)
#define YX_SCALE  ((float)0.17857142857142858) // max(Kh/(0.4*H), Kw/(0.4*W))
#define LAB_SCALE 0.26f
#define L2E       1.44269504f

#define EM_THREADS 512
// dynamic smem: sA[27][840] + sR[840] + sF[6][840] = 34*840 floats
#define EM_SMEM    (34 * CMAX * (int)sizeof(float))   // 114240 bytes

// ---------------- device scratch (no allocs allowed) ----------------
__device__ float  g_pF[K_*6*CMAX];     // cell-blocked pixel features [k][c][p] (~23MB)
__device__ float  g_spFeat[K_*6];      // superpixel features [k][c]
__device__ float  g_part[K_*189];      // per-block partial sums [k][j*7+c] (c=6 -> weight)
__device__ float4 g_sB4[K_*27*2];      // per-cell neighbor coeffs, log2-scaled: {-2*L2E*sp[0..3]},{-2*L2E*sp[4..5], L2E*|sp|^2, nk}

__device__ __forceinline__ float warpSum(float v){
#pragma unroll
    for (int o = 16; o > 0; o >>= 1) v += __shfl_down_sync(0xffffffffu, v, o);
    return v;
}

// fast 2^y, FMA/ALU pipes only. Input already log2-scaled (coefficients carry
// the log2e factor). Valid for y bounded above (~+40 here); low clamp -126.
// Scale trick: bits(z) = 0x4B400000 + n exactly, and 0x4B400000<<23 == 0 mod 2^32,
// so (bits(z)<<23) + 0x3F800000 == (n+127)<<23 for n in [-256,255].
__device__ __forceinline__ float fastExp2(float y){
    y = fmaxf(y, -126.0f);
    float z = y + 12582912.0f;              // 2^23 * 1.5 : forces RN to integer
    float f = y - (z - 12582912.0f);        // f in [-0.5, 0.5]
    float p = 1.33336498e-3f;
    p = fmaf(p, f, 9.61817007e-3f);
    p = fmaf(p, f, 5.55041087e-2f);
    p = fmaf(p, f, 2.40226507e-1f);
    p = fmaf(p, f, 6.93147182e-1f);
    p = fmaf(p, f, 1.0f);
    return p * __int_as_float((__float_as_int(z) << 23) + 0x3F800000);
}

// cell geometry: t in [4kl,4kl+4), y in [y0,y0+ch), x in [14kw,14kw+14)
__device__ __forceinline__ void cellGeom(int k, int& kl, int& kh, int& kw, int& y0, int& ch){
    kl = k / (KH_*KW_);
    kh = (k / KW_) % KH_;
    kw = k % KW_;
    y0 = (256*kh + 17) / 18;
    int y1 = (256*(kh+1) + 17) / 18;
    ch = y1 - y0;  // 14 or 15
}

__device__ __forceinline__ unsigned validMask(int kl, int kh, int kw){
    unsigned vmask = 0;
#pragma unroll
    for (int j = 0; j < 27; j++){
        int dl = j/9 - 1, dh = (j/3)%3 - 1, dw = j%3 - 1;
        if ((unsigned)(kl+dl) < (unsigned)KL_ &&
            (unsigned)(kh+dh) < (unsigned)KH_ &&
            (unsigned)(kw+dw) < (unsigned)KW_) vmask |= (1u << j);
    }
    return vmask;
}

// fill sB[27][8] (log2-scaled): [0..5] = -2*L2E*sp_c, [6] = L2E*|sp|^2, [7] pad.
__device__ __forceinline__ void fillNbr(int tid, int kl, int kh, int kw, float* sB){
    if (tid < 27){
        int dl = tid/9 - 1, dh = (tid/3)%3 - 1, dw = tid%3 - 1;
        int nl = min(max(kl+dl, 0), KL_-1);
        int nh = min(max(kh+dh, 0), KH_-1);
        int nw = min(max(kw+dw, 0), KW_-1);
        int nk = (nl*KH_ + nh)*KW_ + nw;
        float b = 0.f;
#pragma unroll
        for (int c = 0; c < 6; c++){
            float s = g_spFeat[nk*6 + c];
            sB[tid*8 + c] = -2.0f * L2E * s;
            b = fmaf(s, s, b);
        }
        sB[tid*8 + 6] = L2E * b;
        sB[tid*8 + 7] = 0.f;
    }
}

// ---------------- kernel 1: pFeat + blocked copy + sp_init mean ----------------
__global__ void __launch_bounds__(256) pa_kernel(const float* __restrict__ lab,
                                                 float* __restrict__ outPF){
    int k = blockIdx.x, tid = threadIdx.x;
    int kl, kh, kw, y0, ch;
    cellGeom(k, kl, kh, kw, y0, ch);
    int P = 56 * ch;  // 4 * ch * 14

    float s0=0.f,s1=0.f,s2=0.f,s3=0.f,s4=0.f,s5=0.f;
    float* gp = &g_pF[(size_t)k*6*CMAX];
#pragma unroll 1
    for (int p = tid; p < P; p += 256){
        int lx = p % 14, q = p / 14, ly = q % ch, lt = q / ch;
        int t = 4*kl + lt, y = y0 + ly, x = 14*kw + lx;
        int pix = t*HW_ + y*W_ + x;
        float f0 = T_SCALE  * (float)t;
        float f1 = YX_SCALE * (float)y;
        float f2 = YX_SCALE * (float)x;
        float f3 = LAB_SCALE * lab[pix];
        float f4 = LAB_SCALE * lab[NPIX + pix];
        float f5 = LAB_SCALE * lab[2*NPIX + pix];
        outPF[pix]          = f0;
        outPF[NPIX+pix]     = f1;
        outPF[2*NPIX+pix]   = f2;
        outPF[3*NPIX+pix]   = f3;
        outPF[4*NPIX+pix]   = f4;
        outPF[5*NPIX+pix]   = f5;
        gp[p]          = f0;
        gp[CMAX+p]     = f1;
        gp[2*CMAX+p]   = f2;
        gp[3*CMAX+p]   = f3;
        gp[4*CMAX+p]   = f4;
        gp[5*CMAX+p]   = f5;
        s0+=f0; s1+=f1; s2+=f2; s3+=f3; s4+=f4; s5+=f5;
    }
    __shared__ float red[6][8];
    int wid = tid >> 5, lane = tid & 31;
    float sv[6] = {s0,s1,s2,s3,s4,s5};
#pragma unroll
    for (int c = 0; c < 6; c++){
        float v = warpSum(sv[c]);
        if (lane == 0) red[c][wid] = v;
    }
    __syncthreads();
    if (tid < 6){
        float v = 0.f;
#pragma unroll
        for (int w = 0; w < 8; w++) v += red[tid][w];
        g_spFeat[k*6 + tid] = v / (float)P;
    }
}

// ---------------- kernel 2: two-phase fused assoc + accumulate (vectorized) ------
// Phase A (adjacent pixel pairs, float2 ld/st): unnormalized exp -> sA, 1/sum -> sR
// Phase B (9 warps x 3 j-rows, float2 loads): dot products with r folded in -> g_part
__global__ void __launch_bounds__(EM_THREADS, 2) em_kernel(){
    extern __shared__ float smem[];     // sA[27*840] | sR[840] | sF[6*840]
    float* sA = smem;
    float* sR = smem + 27*CMAX;
    float* sF = smem + 28*CMAX;
    int k = blockIdx.x, tid = threadIdx.x;
    int kl, kh, kw, y0, ch;
    cellGeom(k, kl, kh, kw, y0, ch);
    int P = 56 * ch;          // 784 or 840 (always even)

    __shared__ float sB[27*8];
    fillNbr(tid, kl, kh, kw, sB);
    unsigned vmask = validMask(kl, kh, kw);

    // cooperative copy of this block's feature slab (contiguous 6*CMAX floats)
    const float4* gp4 = (const float4*)&g_pF[(size_t)k*6*CMAX];
    float4* sF4 = (float4*)sF;
#pragma unroll 1
    for (int i = tid; i < 6*CMAX/4; i += EM_THREADS) sF4[i] = gp4[i];
    __syncthreads();

    // ---- Phase A: thread handles adjacent pixels p1 = 2*tid, p1+1 ----
    {
        int p1 = 2*tid;
        if (p1 < P){
            float2 F0 = *(const float2*)&sF[p1];
            float2 F1 = *(const float2*)&sF[CMAX+p1];
            float2 F2 = *(const float2*)&sF[2*CMAX+p1];
            float2 F3 = *(const float2*)&sF[3*CMAX+p1];
            float2 F4 = *(const float2*)&sF[4*CMAX+p1];
            float2 F5 = *(const float2*)&sF[5*CMAX+p1];
            // center (j=13) distances (log2 domain)
            float4 c0 = *(const float4*)&sB[13*8];
            float4 c1 = *(const float4*)&sB[13*8 + 4];
            float sh1 = c1.z, sh2 = c1.z;
            sh1 = fmaf(F0.x, c0.x, sh1);  sh2 = fmaf(F0.y, c0.x, sh2);
            sh1 = fmaf(F1.x, c0.y, sh1);  sh2 = fmaf(F1.y, c0.y, sh2);
            sh1 = fmaf(F2.x, c0.z, sh1);  sh2 = fmaf(F2.y, c0.z, sh2);
            sh1 = fmaf(F3.x, c0.w, sh1);  sh2 = fmaf(F3.y, c0.w, sh2);
            sh1 = fmaf(F4.x, c1.x, sh1);  sh2 = fmaf(F4.y, c1.x, sh2);
            sh1 = fmaf(F5.x, c1.y, sh1);  sh2 = fmaf(F5.y, c1.y, sh2);

            float sum1 = 0.f, sum2 = 0.f;
#pragma unroll 3
            for (int j = 0; j < 27; j++){
                float4 b0 = *(const float4*)&sB[j*8];
                float4 b1 = *(const float4*)&sB[j*8 + 4];
                float d1 = b1.z, d2 = b1.z;
                d1 = fmaf(F0.x, b0.x, d1);  d2 = fmaf(F0.y, b0.x, d2);
                d1 = fmaf(F1.x, b0.y, d1);  d2 = fmaf(F1.y, b0.y, d2);
                d1 = fmaf(F2.x, b0.z, d1);  d2 = fmaf(F2.y, b0.z, d2);
                d1 = fmaf(F3.x, b0.w, d1);  d2 = fmaf(F3.y, b0.w, d2);
                d1 = fmaf(F4.x, b1.x, d1);  d2 = fmaf(F4.y, b1.x, d2);
                d1 = fmaf(F5.x, b1.y, d1);  d2 = fmaf(F5.y, b1.y, d2);
                float v1 = fastExp2(sh1 - d1);
                float v2 = fastExp2(sh2 - d2);
                v1 = (vmask & (1u << j)) ? v1 : 0.0f;
                v2 = (vmask & (1u << j)) ? v2 : 0.0f;
                *(float2*)&sA[j*CMAX + p1] = make_float2(v1, v2);
                sum1 += v1; sum2 += v2;
            }
            *(float2*)&sR[p1] = make_float2(1.0f / sum1, 1.0f / sum2);
        }
    }
    __syncthreads();

    // ---- Phase B: 9 warps, warp w handles j = w, w+9, w+18; float2 loads ----
    int wid = tid >> 5, lane = tid & 31;
    if (wid < 9){
        int j1 = wid, j2 = wid + 9, j3 = wid + 18;
        const float* a1row = &sA[j1*CMAX];
        const float* a2row = &sA[j2*CMAX];
        const float* a3row = &sA[j3*CMAX];
        float acc[21];
#pragma unroll
        for (int c = 0; c < 21; c++) acc[c] = 0.f;
#pragma unroll 1
        for (int p = lane*2; p < P; p += 64){
            float2 r  = *(const float2*)&sR[p];
            float2 a1 = *(const float2*)&a1row[p];
            float2 a2 = *(const float2*)&a2row[p];
            float2 a3 = *(const float2*)&a3row[p];
            a1.x *= r.x; a1.y *= r.y;
            a2.x *= r.x; a2.y *= r.y;
            a3.x *= r.x; a3.y *= r.y;
            float2 f0 = *(const float2*)&sF[p];
            float2 f1 = *(const float2*)&sF[CMAX+p];
            float2 f2 = *(const float2*)&sF[2*CMAX+p];
            float2 f3 = *(const float2*)&sF[3*CMAX+p];
            float2 f4 = *(const float2*)&sF[4*CMAX+p];
            float2 f5 = *(const float2*)&sF[5*CMAX+p];
            acc[0]  = fmaf(a1.x, f0.x, acc[0]);   acc[0]  = fmaf(a1.y, f0.y, acc[0]);
            acc[1]  = fmaf(a1.x, f1.x, acc[1]);   acc[1]  = fmaf(a1.y, f1.y, acc[1]);
            acc[2]  = fmaf(a1.x, f2.x, acc[2]);   acc[2]  = fmaf(a1.y, f2.y, acc[2]);
            acc[3]  = fmaf(a1.x, f3.x, acc[3]);   acc[3]  = fmaf(a1.y, f3.y, acc[3]);
            acc[4]  = fmaf(a1.x, f4.x, acc[4]);   acc[4]  = fmaf(a1.y, f4.y, acc[4]);
            acc[5]  = fmaf(a1.x, f5.x, acc[5]);   acc[5]  = fmaf(a1.y, f5.y, acc[5]);
            acc[6] += a1.x + a1.y;
            acc[7]  = fmaf(a2.x, f0.x, acc[7]);   acc[7]  = fmaf(a2.y, f0.y, acc[7]);
            acc[8]  = fmaf(a2.x, f1.x, acc[8]);   acc[8]  = fmaf(a2.y, f1.y, acc[8]);
            acc[9]  = fmaf(a2.x, f2.x, acc[9]);   acc[9]  = fmaf(a2.y, f2.y, acc[9]);
            acc[10] = fmaf(a2.x, f3.x, acc[10]);  acc[10] = fmaf(a2.y, f3.y, acc[10]);
            acc[11] = fmaf(a2.x, f4.x, acc[11]);  acc[11] = fmaf(a2.y, f4.y, acc[11]);
            acc[12] = fmaf(a2.x, f5.x, acc[12]);  acc[12] = fmaf(a2.y, f5.y, acc[12]);
            acc[13] += a2.x + a2.y;
            acc[14] = fmaf(a3.x, f0.x, acc[14]);  acc[14] = fmaf(a3.y, f0.y, acc[14]);
            acc[15] = fmaf(a3.x, f1.x, acc[15]);  acc[15] = fmaf(a3.y, f1.y, acc[15]);
            acc[16] = fmaf(a3.x, f2.x, acc[16]);  acc[16] = fmaf(a3.y, f2.y, acc[16]);
            acc[17] = fmaf(a3.x, f3.x, acc[17]);  acc[17] = fmaf(a3.y, f3.y, acc[17]);
            acc[18] = fmaf(a3.x, f4.x, acc[18]);  acc[18] = fmaf(a3.y, f4.y, acc[18]);
            acc[19] = fmaf(a3.x, f5.x, acc[19]);  acc[19] = fmaf(a3.y, f5.y, acc[19]);
            acc[20] += a3.x + a3.y;
        }
#pragma unroll
        for (int c = 0; c < 7; c++){
            float v = warpSum(acc[c]);
            if (lane == 0) g_part[k*189 + j1*7 + c] = v;
        }
#pragma unroll
        for (int c = 0; c < 7; c++){
            float v = warpSum(acc[7+c]);
            if (lane == 0) g_part[k*189 + j2*7 + c] = v;
        }
#pragma unroll
        for (int c = 0; c < 7; c++){
            float v = warpSum(acc[14+c]);
            if (lane == 0) g_part[k*189 + j3*7 + c] = v;
        }
    }
}

// ---------------- kernel 3: gather partials -> normalized spFeat ----------------
__global__ void norm_kernel(){
    int k = blockIdx.x, lane = threadIdx.x;  // 32 threads, lanes 0..6 used
    int kl, kh, kw, y0, ch;
    cellGeom(k, kl, kh, kw, y0, ch);
    float v = 0.f;
    if (lane < 7){
#pragma unroll
        for (int j = 0; j < 27; j++){
            int dl = j/9 - 1, dh = (j/3)%3 - 1, dw = j%3 - 1;
            int bl = kl - dl, bh = kh - dh, bw = kw - dw;
            if ((unsigned)bl < (unsigned)KL_ &&
                (unsigned)bh < (unsigned)KH_ &&
                (unsigned)bw < (unsigned)KW_){
                int b = (bl*KH_ + bh)*KW_ + bw;
                v += g_part[b*189 + j*7 + lane];
            }
        }
    }
    float w = __shfl_sync(0xffffffffu, v, 6);
    if (lane < 6) g_spFeat[k*6 + lane] = v / fmaxf(w, 1e-12f);
}

// ---------------- kernel 3b: neighbor coeff table (log2-scaled) + spFeat output ---
__global__ void spB_kernel(float* __restrict__ outSP){
    int k = blockIdx.x, j = threadIdx.x;
    if (j < 6) outSP[j*K_ + k] = g_spFeat[k*6 + j];   // spFeat output (transposed)
    if (j >= 27) return;
    int kl = k / (KH_*KW_), kh = (k / KW_) % KH_, kw = k % KW_;
    int dl = j/9 - 1, dh = (j/3)%3 - 1, dw = j%3 - 1;
    int nl = min(max(kl+dl, 0), KL_-1);
    int nh = min(max(kh+dh, 0), KH_-1);
    int nw = min(max(kw+dw, 0), KW_-1);
    int nk = (nl*KH_ + nh)*KW_ + nw;
    float s[6]; float b = 0.f;
#pragma unroll
    for (int c = 0; c < 6; c++){ s[c] = g_spFeat[nk*6 + c]; b = fmaf(s[c], s[c], b); }
    g_sB4[(k*27 + j)*2]     = make_float4(-2.f*L2E*s[0], -2.f*L2E*s[1],
                                          -2.f*L2E*s[2], -2.f*L2E*s[3]);
    g_sB4[(k*27 + j)*2 + 1] = make_float4(-2.f*L2E*s[4], -2.f*L2E*s[5],
                                          L2E*b, (float)nk);
}

// ---------------- kernel 4: final assoc + argmax, global-pixel coalesced ----------------
__global__ void __launch_bounds__(256) final_kernel(const float* __restrict__ outPF,
                                                    float* __restrict__ outA,
                                                    float* __restrict__ outF){
    int pix = blockIdx.x * 256 + threadIdx.x;   // grid = NPIX/256
    int t = pix / HW_; int rr = pix - t*HW_;
    int y = rr / W_;   int x  = rr - y*W_;
    int kl = t >> 2;
    int kh = (y * 18) >> 8;
    int kw = x / 14;
    int k  = (kl*KH_ + kh)*KW_ + kw;
    unsigned vmask = validMask(kl, kh, kw);

    float f0 = outPF[pix];
    float f1 = outPF[NPIX + pix];
    float f2 = outPF[2*NPIX + pix];
    float f3 = outPF[3*NPIX + pix];
    float f4 = outPF[4*NPIX + pix];
    float f5 = outPF[5*NPIX + pix];

    // shift = center (j=13) distance (always valid; log2 domain)
    float4 c0 = __ldg(&g_sB4[(k*27 + 13)*2]);
    float4 c1 = __ldg(&g_sB4[(k*27 + 13)*2 + 1]);
    float shift = c1.z;
    shift = fmaf(f0, c0.x, shift);
    shift = fmaf(f1, c0.y, shift);
    shift = fmaf(f2, c0.z, shift);
    shift = fmaf(f3, c0.w, shift);
    shift = fmaf(f4, c1.x, shift);
    shift = fmaf(f5, c1.y, shift);

    float e[27];
    float sum = 0.f;
    float best = -1.f; int bj = 0;
#pragma unroll
    for (int j = 0; j < 27; j++){
        float4 b0 = __ldg(&g_sB4[(k*27 + j)*2]);
        float4 b1 = __ldg(&g_sB4[(k*27 + j)*2 + 1]);
        float dd = b1.z;
        dd = fmaf(f0, b0.x, dd);
        dd = fmaf(f1, b0.y, dd);
        dd = fmaf(f2, b0.z, dd);
        dd = fmaf(f3, b0.w, dd);
        dd = fmaf(f4, b1.x, dd);
        dd = fmaf(f5, b1.y, dd);
        float v = fastExp2(shift - dd);
        v = (vmask & (1u << j)) ? v : 0.0f;
        e[j] = v; sum += v;
        if (v > best){ best = v; bj = j; }   // argmax of e == argmax of a (r > 0)
    }
    float r = 1.0f / sum;
#pragma unroll
    for (int j = 0; j < 27; j++)
        outA[(size_t)j*NPIX + pix] = e[j] * r;
    outF[pix] = __ldg(&g_sB4[(k*27 + bj)*2 + 1]).w;
}

// ---------------- launcher ----------------
extern "C" void kernel_launch(void* const* d_in, const int* in_sizes, int n_in,
                              void* d_out, int out_size){
    const float* lab = (const float*)d_in[0];
    if (n_in > 1 && in_sizes[0] != 3*NPIX) lab = (const float*)d_in[1];

    float* out   = (float*)d_out;
    float* outPF = out;                          // 6*N   = 5505024
    float* outSP = out + (size_t)6*NPIX;         // 6*K   = 6912
    float* outA  = outSP + 6*K_;                 // 27*N  = 24772608
    float* outF  = outA + (size_t)27*NPIX;       // N     = 917504

    cudaFuncSetAttribute(em_kernel, cudaFuncAttributeMaxDynamicSharedMemorySize, EM_SMEM);

    pa_kernel<<<K_, 256>>>(lab, outPF);
    for (int it = 0; it < 4; it++){
        em_kernel<<<K_, EM_THREADS, EM_SMEM>>>();
        norm_kernel<<<K_, 32>>>();
    }
    spB_kernel<<<K_, 32>>>(outSP);
    final_kernel<<<NPIX/256, 256>>>(outPF, outA, outF);
}

// round 17
// speedup vs baseline: 1.4594x; 1.2212x over previous
#include <cuda_runtime.h>

// ---------------- problem constants ----------------
#define L_   8
#define H_   256
#define W_   448
#define KL_  2
#define KH_  18
#define KW_  32
#define K_   1152              // KL*KH*KW
#define HW_  (H_*W_)           // 114688
#define NPIX (L_*HW_)          // 917504
#define CMAX 840               // max pixels per cell: 4 * 15 * 14

#define T_SCALE   0.625f                       // Kl/(0.4*L)
#define YX_SCALE  ((float)0.17857142857142858) // max(Kh/(0.4*H), Kw/(0.4*W))
#define LAB_SCALE 0.26f
#define L2E       1.44269504f

#define EM_THREADS 512
// dynamic smem: sA[27][840] + sR[840] + sF[6][840] = 34*840 floats
#define EM_SMEM    (34 * CMAX * (int)sizeof(float))   // 114240 bytes

// ---------------- device scratch (no allocs allowed) ----------------
__device__ float  g_pF[K_*6*CMAX];     // cell-blocked pixel features [k][c][p] (~23MB)
__device__ float  g_spFeat[K_*6];      // superpixel features [k][c]
__device__ float  g_part[K_*189];      // per-block partial sums [k][j*7+c]; only VALID j channels written/read
__device__ float4 g_sB4[K_*27*2];      // per-cell neighbor coeffs, log2-scaled

__device__ __forceinline__ float warpSum(float v){
#pragma unroll
    for (int o = 16; o > 0; o >>= 1) v += __shfl_down_sync(0xffffffffu, v, o);
    return v;
}

// fast 2^y, FMA/ALU pipes only. Input already log2-scaled. Low clamp -126.
__device__ __forceinline__ float fastExp2(float y){
    y = fmaxf(y, -126.0f);
    float z = y + 12582912.0f;              // 2^23 * 1.5 : forces RN to integer
    float f = y - (z - 12582912.0f);        // f in [-0.5, 0.5]
    float p = 1.33336498e-3f;
    p = fmaf(p, f, 9.61817007e-3f);
    p = fmaf(p, f, 5.55041087e-2f);
    p = fmaf(p, f, 2.40226507e-1f);
    p = fmaf(p, f, 6.93147182e-1f);
    p = fmaf(p, f, 1.0f);
    return p * __int_as_float((__float_as_int(z) << 23) + 0x3F800000);
}

// cell geometry: t in [4kl,4kl+4), y in [y0,y0+ch), x in [14kw,14kw+14)
__device__ __forceinline__ void cellGeom(int k, int& kl, int& kh, int& kw, int& y0, int& ch){
    kl = k / (KH_*KW_);
    kh = (k / KW_) % KH_;
    kw = k % KW_;
    y0 = (256*kh + 17) / 18;
    int y1 = (256*(kh+1) + 17) / 18;
    ch = y1 - y0;  // 14 or 15
}

__device__ __forceinline__ unsigned validMask(int kl, int kh, int kw){
    unsigned vmask = 0;
#pragma unroll
    for (int j = 0; j < 27; j++){
        int dl = j/9 - 1, dh = (j/3)%3 - 1, dw = j%3 - 1;
        if ((unsigned)(kl+dl) < (unsigned)KL_ &&
            (unsigned)(kh+dh) < (unsigned)KH_ &&
            (unsigned)(kw+dw) < (unsigned)KW_) vmask |= (1u << j);
    }
    return vmask;
}

// ---------------- kernel 1: pFeat + blocked copy + sp_init mean ----------------
__global__ void __launch_bounds__(256) pa_kernel(const float* __restrict__ lab,
                                                 float* __restrict__ outPF){
    int k = blockIdx.x, tid = threadIdx.x;
    int kl, kh, kw, y0, ch;
    cellGeom(k, kl, kh, kw, y0, ch);
    int P = 56 * ch;  // 4 * ch * 14

    float s0=0.f,s1=0.f,s2=0.f,s3=0.f,s4=0.f,s5=0.f;
    float* gp = &g_pF[(size_t)k*6*CMAX];
#pragma unroll 1
    for (int p = tid; p < P; p += 256){
        int lx = p % 14, q = p / 14, ly = q % ch, lt = q / ch;
        int t = 4*kl + lt, y = y0 + ly, x = 14*kw + lx;
        int pix = t*HW_ + y*W_ + x;
        float f0 = T_SCALE  * (float)t;
        float f1 = YX_SCALE * (float)y;
        float f2 = YX_SCALE * (float)x;
        float f3 = LAB_SCALE * lab[pix];
        float f4 = LAB_SCALE * lab[NPIX + pix];
        float f5 = LAB_SCALE * lab[2*NPIX + pix];
        outPF[pix]          = f0;
        outPF[NPIX+pix]     = f1;
        outPF[2*NPIX+pix]   = f2;
        outPF[3*NPIX+pix]   = f3;
        outPF[4*NPIX+pix]   = f4;
        outPF[5*NPIX+pix]   = f5;
        gp[p]          = f0;
        gp[CMAX+p]     = f1;
        gp[2*CMAX+p]   = f2;
        gp[3*CMAX+p]   = f3;
        gp[4*CMAX+p]   = f4;
        gp[5*CMAX+p]   = f5;
        s0+=f0; s1+=f1; s2+=f2; s3+=f3; s4+=f4; s5+=f5;
    }
    __shared__ float red[6][8];
    int wid = tid >> 5, lane = tid & 31;
    float sv[6] = {s0,s1,s2,s3,s4,s5};
#pragma unroll
    for (int c = 0; c < 6; c++){
        float v = warpSum(sv[c]);
        if (lane == 0) red[c][wid] = v;
    }
    __syncthreads();
    if (tid < 6){
        float v = 0.f;
#pragma unroll
        for (int w = 0; w < 8; w++) v += red[tid][w];
        g_spFeat[k*6 + tid] = v / (float)P;
    }
}

// ---------------- kernel 2: compacted-neighbor two-phase assoc + accumulate ------
// Preamble: compacted sB rows for VALID j only (pos by popc prefix); pad = j*7
// Phase A (pixel pairs, float2): loop r < nv, no masks -> sA rows [0..nv), sR
// Phase B (9 warps x rows {w, w+9}): guarded by nv, writes g_part valid channels
__global__ void __launch_bounds__(EM_THREADS, 2) em_kernel(){
    extern __shared__ float smem[];     // sA[27*840] | sR[840] | sF[6*840]
    float* sA = smem;
    float* sR = smem + 27*CMAX;
    float* sF = smem + 28*CMAX;
    int k = blockIdx.x, tid = threadIdx.x;
    int kl, kh, kw, y0, ch;
    cellGeom(k, kl, kh, kw, y0, ch);
    int P = 56 * ch;          // 784 or 840 (always even)

    __shared__ float sB[27*8];
    unsigned vmask = validMask(kl, kh, kw);
    int nv = __popc(vmask);                       // 8, 12, or 18 (block-uniform)
    int centerPos = __popc(vmask & 0x1FFFu);      // compacted position of j=13

    if (tid < 27 && ((vmask >> tid) & 1u)){
        int pos = __popc(vmask & ((1u << tid) - 1u));
        int dl = tid/9 - 1, dh = (tid/3)%3 - 1, dw = tid%3 - 1;
        int nk = ((kl+dl)*KH_ + (kh+dh))*KW_ + (kw+dw);   // valid => in range
        float b = 0.f;
#pragma unroll
        for (int c = 0; c < 6; c++){
            float s = g_spFeat[nk*6 + c];
            sB[pos*8 + c] = -2.0f * L2E * s;
            b = fmaf(s, s, b);
        }
        sB[pos*8 + 6] = L2E * b;
        sB[pos*8 + 7] = (float)(tid * 7);         // g_part channel base for this j
    }

    // cooperative copy of this block's feature slab (contiguous 6*CMAX floats)
    const float4* gp4 = (const float4*)&g_pF[(size_t)k*6*CMAX];
    float4* sF4 = (float4*)sF;
#pragma unroll 1
    for (int i = tid; i < 6*CMAX/4; i += EM_THREADS) sF4[i] = gp4[i];
    __syncthreads();

    // ---- Phase A: thread handles adjacent pixels p1 = 2*tid, p1+1 ----
    {
        int p1 = 2*tid;
        if (p1 < P){
            float2 F0 = *(const float2*)&sF[p1];
            float2 F1 = *(const float2*)&sF[CMAX+p1];
            float2 F2 = *(const float2*)&sF[2*CMAX+p1];
            float2 F3 = *(const float2*)&sF[3*CMAX+p1];
            float2 F4 = *(const float2*)&sF[4*CMAX+p1];
            float2 F5 = *(const float2*)&sF[5*CMAX+p1];
            float4 c0 = *(const float4*)&sB[centerPos*8];
            float4 c1 = *(const float4*)&sB[centerPos*8 + 4];
            float sh1 = c1.z, sh2 = c1.z;
            sh1 = fmaf(F0.x, c0.x, sh1);  sh2 = fmaf(F0.y, c0.x, sh2);
            sh1 = fmaf(F1.x, c0.y, sh1);  sh2 = fmaf(F1.y, c0.y, sh2);
            sh1 = fmaf(F2.x, c0.z, sh1);  sh2 = fmaf(F2.y, c0.z, sh2);
            sh1 = fmaf(F3.x, c0.w, sh1);  sh2 = fmaf(F3.y, c0.w, sh2);
            sh1 = fmaf(F4.x, c1.x, sh1);  sh2 = fmaf(F4.y, c1.x, sh2);
            sh1 = fmaf(F5.x, c1.y, sh1);  sh2 = fmaf(F5.y, c1.y, sh2);

            float sum1 = 0.f, sum2 = 0.f;
#pragma unroll 3
            for (int r = 0; r < nv; r++){
                float4 b0 = *(const float4*)&sB[r*8];
                float4 b1 = *(const float4*)&sB[r*8 + 4];
                float d1 = b1.z, d2 = b1.z;
                d1 = fmaf(F0.x, b0.x, d1);  d2 = fmaf(F0.y, b0.x, d2);
                d1 = fmaf(F1.x, b0.y, d1);  d2 = fmaf(F1.y, b0.y, d2);
                d1 = fmaf(F2.x, b0.z, d1);  d2 = fmaf(F2.y, b0.z, d2);
                d1 = fmaf(F3.x, b0.w, d1);  d2 = fmaf(F3.y, b0.w, d2);
                d1 = fmaf(F4.x, b1.x, d1);  d2 = fmaf(F4.y, b1.x, d2);
                d1 = fmaf(F5.x, b1.y, d1);  d2 = fmaf(F5.y, b1.y, d2);
                float v1 = fastExp2(sh1 - d1);
                float v2 = fastExp2(sh2 - d2);
                *(float2*)&sA[r*CMAX + p1] = make_float2(v1, v2);
                sum1 += v1; sum2 += v2;
            }
            *(float2*)&sR[p1] = make_float2(1.0f / sum1, 1.0f / sum2);
        }
    }
    __syncthreads();

    // ---- Phase B: 9 warps, warp w handles compacted rows w and w+9 ----
    int wid = tid >> 5, lane = tid & 31;
    if (wid < 9 && wid < nv){
        int r1 = wid, r2 = wid + 9;
        bool h2 = (r2 < nv);
        const float* a1row = &sA[r1*CMAX];
        const float* a2row = &sA[(h2 ? r2 : r1)*CMAX];
        float acc[14];
#pragma unroll
        for (int c = 0; c < 14; c++) acc[c] = 0.f;
#pragma unroll 1
        for (int p = lane*2; p < P; p += 64){
            float2 r  = *(const float2*)&sR[p];
            float2 a1 = *(const float2*)&a1row[p];
            float2 a2 = *(const float2*)&a2row[p];
            a1.x *= r.x; a1.y *= r.y;
            a2.x *= r.x; a2.y *= r.y;
            float2 f0 = *(const float2*)&sF[p];
            float2 f1 = *(const float2*)&sF[CMAX+p];
            float2 f2 = *(const float2*)&sF[2*CMAX+p];
            float2 f3 = *(const float2*)&sF[3*CMAX+p];
            float2 f4 = *(const float2*)&sF[4*CMAX+p];
            float2 f5 = *(const float2*)&sF[5*CMAX+p];
            acc[0]  = fmaf(a1.x, f0.x, acc[0]);   acc[0]  = fmaf(a1.y, f0.y, acc[0]);
            acc[1]  = fmaf(a1.x, f1.x, acc[1]);   acc[1]  = fmaf(a1.y, f1.y, acc[1]);
            acc[2]  = fmaf(a1.x, f2.x, acc[2]);   acc[2]  = fmaf(a1.y, f2.y, acc[2]);
            acc[3]  = fmaf(a1.x, f3.x, acc[3]);   acc[3]  = fmaf(a1.y, f3.y, acc[3]);
            acc[4]  = fmaf(a1.x, f4.x, acc[4]);   acc[4]  = fmaf(a1.y, f4.y, acc[4]);
            acc[5]  = fmaf(a1.x, f5.x, acc[5]);   acc[5]  = fmaf(a1.y, f5.y, acc[5]);
            acc[6] += a1.x + a1.y;
            acc[7]  = fmaf(a2.x, f0.x, acc[7]);   acc[7]  = fmaf(a2.y, f0.y, acc[7]);
            acc[8]  = fmaf(a2.x, f1.x, acc[8]);   acc[8]  = fmaf(a2.y, f1.y, acc[8]);
            acc[9]  = fmaf(a2.x, f2.x, acc[9]);   acc[9]  = fmaf(a2.y, f2.y, acc[9]);
            acc[10] = fmaf(a2.x, f3.x, acc[10]);  acc[10] = fmaf(a2.y, f3.y, acc[10]);
            acc[11] = fmaf(a2.x, f4.x, acc[11]);  acc[11] = fmaf(a2.y, f4.y, acc[11]);
            acc[12] = fmaf(a2.x, f5.x, acc[12]);  acc[12] = fmaf(a2.y, f5.y, acc[12]);
            acc[13] += a2.x + a2.y;
        }
        int j7a = (int)sB[r1*8 + 7];
#pragma unroll
        for (int c = 0; c < 7; c++){
            float v = warpSum(acc[c]);
            if (lane == 0) g_part[k*189 + j7a + c] = v;
        }
        if (h2){
            int j7b = (int)sB[r2*8 + 7];
#pragma unroll
            for (int c = 0; c < 7; c++){
                float v = warpSum(acc[7+c]);
                if (lane == 0) g_part[k*189 + j7b + c] = v;
            }
        }
    }
}

// ---------------- kernel 3: gather partials -> normalized spFeat ----------------
// Reads only channels (b, j) whose target b+d_j == k is in range => always written.
__global__ void norm_kernel(){
    int k = blockIdx.x, lane = threadIdx.x;  // 32 threads, lanes 0..6 used
    int kl, kh, kw, y0, ch;
    cellGeom(k, kl, kh, kw, y0, ch);
    float v = 0.f;
    if (lane < 7){
#pragma unroll
        for (int j = 0; j < 27; j++){
            int dl = j/9 - 1, dh = (j/3)%3 - 1, dw = j%3 - 1;
            int bl = kl - dl, bh = kh - dh, bw = kw - dw;
            if ((unsigned)bl < (unsigned)KL_ &&
                (unsigned)bh < (unsigned)KH_ &&
                (unsigned)bw < (unsigned)KW_){
                int b = (bl*KH_ + bh)*KW_ + bw;
                v += g_part[b*189 + j*7 + lane];
            }
        }
    }
    float w = __shfl_sync(0xffffffffu, v, 6);
    if (lane < 6) g_spFeat[k*6 + lane] = v / fmaxf(w, 1e-12f);
}

// ---------------- kernel 3b: neighbor coeff table (log2-scaled) + spFeat output ---
__global__ void spB_kernel(float* __restrict__ outSP){
    int k = blockIdx.x, j = threadIdx.x;
    if (j < 6) outSP[j*K_ + k] = g_spFeat[k*6 + j];   // spFeat output (transposed)
    if (j >= 27) return;
    int kl = k / (KH_*KW_), kh = (k / KW_) % KH_, kw = k % KW_;
    int dl = j/9 - 1, dh = (j/3)%3 - 1, dw = j%3 - 1;
    int nl = min(max(kl+dl, 0), KL_-1);
    int nh = min(max(kh+dh, 0), KH_-1);
    int nw = min(max(kw+dw, 0), KW_-1);
    int nk = (nl*KH_ + nh)*KW_ + nw;
    float s[6]; float b = 0.f;
#pragma unroll
    for (int c = 0; c < 6; c++){ s[c] = g_spFeat[nk*6 + c]; b = fmaf(s[c], s[c], b); }
    g_sB4[(k*27 + j)*2]     = make_float4(-2.f*L2E*s[0], -2.f*L2E*s[1],
                                          -2.f*L2E*s[2], -2.f*L2E*s[3]);
    g_sB4[(k*27 + j)*2 + 1] = make_float4(-2.f*L2E*s[4], -2.f*L2E*s[5],
                                          L2E*b, (float)nk);
}

// ---------------- kernel 4: final assoc + argmax, global-pixel coalesced ----------------
__global__ void __launch_bounds__(256) final_kernel(const float* __restrict__ outPF,
                                                    float* __restrict__ outA,
                                                    float* __restrict__ outF){
    int pix = blockIdx.x * 256 + threadIdx.x;   // grid = NPIX/256
    int t = pix / HW_; int rr = pix - t*HW_;
    int y = rr / W_;   int x  = rr - y*W_;
    int kl = t >> 2;
    int kh = (y * 18) >> 8;
    int kw = x / 14;
    int k  = (kl*KH_ + kh)*KW_ + kw;
    unsigned vmask = validMask(kl, kh, kw);

    float f0 = outPF[pix];
    float f1 = outPF[NPIX + pix];
    float f2 = outPF[2*NPIX + pix];
    float f3 = outPF[3*NPIX + pix];
    float f4 = outPF[4*NPIX + pix];
    float f5 = outPF[5*NPIX + pix];

    // shift = center (j=13) distance (always valid; log2 domain)
    float4 c0 = __ldg(&g_sB4[(k*27 + 13)*2]);
    float4 c1 = __ldg(&g_sB4[(k*27 + 13)*2 + 1]);
    float shift = c1.z;
    shift = fmaf(f0, c0.x, shift);
    shift = fmaf(f1, c0.y, shift);
    shift = fmaf(f2, c0.z, shift);
    shift = fmaf(f3, c0.w, shift);
    shift = fmaf(f4, c1.x, shift);
    shift = fmaf(f5, c1.y, shift);

    float e[27];
    float sum = 0.f;
    float best = -1.f; int bj = 0;
#pragma unroll
    for (int j = 0; j < 27; j++){
        float4 b0 = __ldg(&g_sB4[(k*27 + j)*2]);
        float4 b1 = __ldg(&g_sB4[(k*27 + j)*2 + 1]);
        float dd = b1.z;
        dd = fmaf(f0, b0.x, dd);
        dd = fmaf(f1, b0.y, dd);
        dd = fmaf(f2, b0.z, dd);
        dd = fmaf(f3, b0.w, dd);
        dd = fmaf(f4, b1.x, dd);
        dd = fmaf(f5, b1.y, dd);
        float v = fastExp2(shift - dd);
        v = (vmask & (1u << j)) ? v : 0.0f;
        e[j] = v; sum += v;
        if (v > best){ best = v; bj = j; }   // argmax of e == argmax of a (r > 0)
    }
    float r = 1.0f / sum;
#pragma unroll
    for (int j = 0; j < 27; j++)
        outA[(size_t)j*NPIX + pix] = e[j] * r;
    outF[pix] = __ldg(&g_sB4[(k*27 + bj)*2 + 1]).w;
}

// ---------------- launcher ----------------
extern "C" void kernel_launch(void* const* d_in, const int* in_sizes, int n_in,
                              void* d_out, int out_size){
    const float* lab = (const float*)d_in[0];
    if (n_in > 1 && in_sizes[0] != 3*NPIX) lab = (const float*)d_in[1];

    float* out   = (float*)d_out;
    float* outPF = out;                          // 6*N   = 5505024
    float* outSP = out + (size_t)6*NPIX;         // 6*K   = 6912
    float* outA  = outSP + 6*K_;                 // 27*N  = 24772608
    float* outF  = outA + (size_t)27*NPIX;       // N     = 917504

    cudaFuncSetAttribute(em_kernel, cudaFuncAttributeMaxDynamicSharedMemorySize, EM_SMEM);

    pa_kernel<<<K_, 256>>>(lab, outPF);
    for (int it = 0; it < 4; it++){
        em_kernel<<<K_, EM_THREADS, EM_SMEM>>>();
        norm_kernel<<<K_, 32>>>();
    }
    spB_kernel<<<K_, 32>>>(outSP);
    final_kernel<<<NPIX/256, 256>>>(outPF, outA, outF);
}